// round 7
// baseline (speedup 1.0000x reference)
#include <cuda_runtime.h>
#include <cuda_bf16.h>
#include <cstdint>
#include <math.h>

// Problem constants (fixed shapes)
#define NROWS 65536
#define DDIM  512
#define CCLS  64

#define GA 128                 // kernel A blocks
#define GC 512                 // kernel C blocks (128 rows each)

// ---------------- device scratch ----------------
__device__ float g_psums[GA * CCLS * DDIM];      // per-block partial class sums
__device__ float g_pcnt [GA * CCLS];             // per-block partial class counts
__device__ __nv_bfloat16 g_pHi[CCLS * DDIM];     // prototypes hi (bf16) [c][d]
__device__ __nv_bfloat16 g_pLo[CCLS * DDIM];     // prototypes lo (bf16)
__device__ float g_p2[CCLS];                     // ||p_c||^2 (fp32)
__device__ float g_bl[GC];                       // per-block loss partial
__device__ float g_ba[GC];                       // per-block accuracy partial

// ---------------- helpers ----------------
__device__ __forceinline__ uint32_t smem_u32(const void* p) {
    uint32_t a;
    asm("{ .reg .u64 t; cvta.to.shared.u64 t, %1; cvt.u32.u64 %0, t; }" : "=r"(a) : "l"(p));
    return a;
}
__device__ __forceinline__ uint32_t bf16x2_of(float lo, float hi) {
    uint32_t r;
    asm("cvt.rn.bf16x2.f32 %0, %1, %2;" : "=r"(r) : "f"(hi), "f"(lo));
    return r;
}
__device__ __forceinline__ float hf_lo(uint32_t h) { return __uint_as_float(h << 16); }
__device__ __forceinline__ float hf_hi(uint32_t h) { return __uint_as_float(h & 0xFFFF0000u); }

#define SWZ(off) ((off) ^ (((off) >> 3) & 0x70))

#define STS128(a, r0, r1, r2, r3) \
    asm volatile("st.shared.v4.b32 [%0], {%1,%2,%3,%4};" :: "r"(a), "r"(r0), "r"(r1), "r"(r2), "r"(r3) : "memory")

#define LDSM4(r, a) \
    asm volatile("ldmatrix.sync.aligned.m8n8.x4.shared.b16 {%0,%1,%2,%3}, [%4];" \
        : "=r"((r)[0]), "=r"((r)[1]), "=r"((r)[2]), "=r"((r)[3]) : "r"(a))

__device__ __forceinline__ void mma_bf16(float* d, const uint32_t* a, uint32_t b0, uint32_t b1) {
    asm volatile("mma.sync.aligned.m16n8k16.row.col.f32.bf16.bf16.f32 "
        "{%0,%1,%2,%3}, {%4,%5,%6,%7}, {%8,%9}, {%0,%1,%2,%3};"
        : "+f"(d[0]), "+f"(d[1]), "+f"(d[2]), "+f"(d[3])
        : "r"(a[0]), "r"(a[1]), "r"(a[2]), "r"(a[3]), "r"(b0), "r"(b1));
}

// ============================================================
// Kernel A: per-block segment sums (race-free column slices)
// ============================================================
__global__ void __launch_bounds__(256)
kA(const float* __restrict__ emb, const int* __restrict__ labels) {
    extern __shared__ float s[];
    float* acc  = s;
    float* cnt  = s + CCLS * DDIM;
    int*   slab = (int*)(s + CCLS * DDIM + CCLS);

    int t = threadIdx.x;
    int base = blockIdx.x * 512;

    for (int i = t * 4; i < CCLS * DDIM; i += 256 * 4)
        *(float4*)(acc + i) = make_float4(0.f, 0.f, 0.f, 0.f);
    if (t < CCLS) cnt[t] = 0.f;
    slab[t]       = labels[base + t] & (CCLS - 1);
    slab[t + 256] = labels[base + t + 256] & (CCLS - 1);
    __syncthreads();

    atomicAdd(&cnt[slab[t]], 1.f);
    atomicAdd(&cnt[slab[t + 256]], 1.f);

    const float* eBase = emb + (size_t)base * DDIM + t * 2;
#pragma unroll 4
    for (int r = 0; r < 512; r++) {
        float2 v = *(const float2*)(eBase + (size_t)r * DDIM);
        int l = slab[r];
        float2* a = (float2*)(acc + l * DDIM + t * 2);
        float2 c = *a;
        c.x += v.x; c.y += v.y;
        *a = c;
    }
    __syncthreads();

    float* out = g_psums + (size_t)blockIdx.x * (CCLS * DDIM);
    for (int i = t * 4; i < CCLS * DDIM; i += 256 * 4)
        *(float4*)(out + i) = *(float4*)(acc + i);
    if (t < CCLS) g_pcnt[blockIdx.x * CCLS + t] = cnt[t];
}

// ============================================================
// Kernel B: reduce partials -> prototypes (bf16 hi/lo) + p2
// ============================================================
__global__ void __launch_bounds__(512)
kB() {
    int c = blockIdx.x;
    int d = threadIdx.x;
    __shared__ float scnt[128];
    __shared__ float sred[512];

    if (d < 128) scnt[d] = g_pcnt[d * CCLS + c];
    __syncthreads();
    for (int s = 64; s >= 1; s >>= 1) {
        if (d < s) scnt[d] += scnt[d + s];
        __syncthreads();
    }
    float cnt = scnt[0];

    float sum = 0.f;
    const float* base = g_psums + (size_t)c * DDIM + d;
#pragma unroll 8
    for (int g = 0; g < GA; g++) sum += base[(size_t)g * (CCLS * DDIM)];
    float proto = sum / cnt;

    __nv_bfloat16 h = __float2bfloat16(proto);
    float hf = __bfloat162float(h);
    g_pHi[c * DDIM + d] = h;
    g_pLo[c * DDIM + d] = __float2bfloat16(proto - hf);

    sred[d] = proto * proto;
    __syncthreads();
    for (int s = 256; s >= 1; s >>= 1) {
        if (d < s) sred[d] += sred[d + s];
        __syncthreads();
    }
    if (d == 0) g_p2[c] = sred[0];
}

// ============================================================
// Kernel C: HMMA (mma.sync bf16 hi/lo) GEMM 128x64 per CTA over
//           K=512 in 8 chunks + fused softmax/NLL/argmax
// ============================================================
// smem byte offsets (from 1024-aligned base):
#define OFF_AHI   0            // 128x64 bf16 = 16KB
#define OFF_ALO   16384
#define OFF_BHI   32768        // 64x64 bf16 = 8KB
#define OFF_BLO   40960
//   stage total 49152; logits [128][68] f32 = 34816 reuses [0..)
#define OFF_LOG   0
#define OFF_E2    49152        // 256 floats (per (row,half) partials)
#define OFF_P2    50176        // 64 floats
#define OFF_WL    50432        // 8 floats
#define OFF_WA    50464        // 8 floats
#define SMC_BYTES (50496 + 1024)

__global__ void __launch_bounds__(256, 2)
kC(const float* __restrict__ emb, const int* __restrict__ labels) {
    extern __shared__ __align__(16) unsigned char smraw[];
    uint32_t raw = smem_u32(smraw);
    uint32_t base = (raw + 1023) & ~1023u;
    float* smf = (float*)(smraw + (base - raw));   // float view of aligned base

    const int t = threadIdx.x;
    const int wid = t >> 5, lane = t & 31;
    const int blk = blockIdx.x;

    const int Rb = (wid >> 1) * 32;   // warp row base (0..96)
    const int Cb = (wid & 1) * 32;    // warp col base (0 or 32)

    const int row  = t >> 1;          // 0..127 (A loader row)
    const int half = t & 1;           // 32-col half
    const float* aptr = emb + ((size_t)(blk * 128 + row)) * DDIM + half * 32;
    float e2acc = 0.f;

    float acc[2][4][4];
#pragma unroll
    for (int i = 0; i < 2; i++)
#pragma unroll
        for (int j = 0; j < 4; j++)
#pragma unroll
            for (int k = 0; k < 4; k++) acc[i][j][k] = 0.f;

    // per-lane ldmatrix offsets (constant across chunks except ks/k)
    const int arowoff = (lane & 7) + ((lane >> 3) & 1) * 8;
    const int akoff   = ((lane >> 4) & 1) * 8;
    const int bnoff   = (lane & 7) + ((lane >> 4) & 1) * 8;
    const int bkoff   = ((lane >> 3) & 1) * 8;

    for (int kt = 0; kt < 8; kt++) {
        // ---- A: load 32 f32, convert to bf16 hi/lo, swizzled STS
        float4 av[8];
#pragma unroll
        for (int i = 0; i < 8; i++) av[i] = *(const float4*)(aptr + kt * 64 + i * 4);
        // ---- B: copy hi/lo chunk rows
        uint4 bhv[2], blv[2];
#pragma unroll
        for (int i = 0; i < 2; i++) {
            int chunk = t * 2 + i;          // 0..511
            int brow = chunk >> 3;          // class 0..63
            int bcg  = chunk & 7;           // 16B chunk in 128B row
            size_t go = (size_t)brow * DDIM + kt * 64 + bcg * 8;
            bhv[i] = *(const uint4*)(g_pHi + go);
            blv[i] = *(const uint4*)(g_pLo + go);
        }

#pragma unroll
        for (int j = 0; j < 4; j++) {
            float4 v0 = av[2 * j], v1 = av[2 * j + 1];
            e2acc += v0.x * v0.x + v0.y * v0.y + v0.z * v0.z + v0.w * v0.w
                   + v1.x * v1.x + v1.y * v1.y + v1.z * v1.z + v1.w * v1.w;
            uint32_t h0 = bf16x2_of(v0.x, v0.y);
            uint32_t h1 = bf16x2_of(v0.z, v0.w);
            uint32_t h2 = bf16x2_of(v1.x, v1.y);
            uint32_t h3 = bf16x2_of(v1.z, v1.w);
            uint32_t l0 = bf16x2_of(v0.x - hf_lo(h0), v0.y - hf_hi(h0));
            uint32_t l1 = bf16x2_of(v0.z - hf_lo(h1), v0.w - hf_hi(h1));
            uint32_t l2 = bf16x2_of(v1.x - hf_lo(h2), v1.y - hf_hi(h2));
            uint32_t l3 = bf16x2_of(v1.z - hf_lo(h3), v1.w - hf_hi(h3));
            uint32_t boff = (uint32_t)(row * 128 + half * 64 + j * 16);
            uint32_t sw = SWZ(boff);
            STS128(base + OFF_AHI + sw, h0, h1, h2, h3);
            STS128(base + OFF_ALO + sw, l0, l1, l2, l3);
        }
#pragma unroll
        for (int i = 0; i < 2; i++) {
            int chunk = t * 2 + i;
            int brow = chunk >> 3, bcg = chunk & 7;
            uint32_t sw = SWZ((uint32_t)(brow * 128 + bcg * 16));
            STS128(base + OFF_BHI + sw, bhv[i].x, bhv[i].y, bhv[i].z, bhv[i].w);
            STS128(base + OFF_BLO + sw, blv[i].x, blv[i].y, blv[i].z, blv[i].w);
        }
        __syncthreads();

        // ---- compute: 4 k16 steps
#pragma unroll
        for (int ks = 0; ks < 4; ks++) {
            uint32_t ah[2][4], al[2][4];
#pragma unroll
            for (int mt = 0; mt < 2; mt++) {
                uint32_t off = (uint32_t)((Rb + 16 * mt + arowoff) * 128 + (ks * 16 + akoff) * 2);
                uint32_t sw = SWZ(off);
                LDSM4(ah[mt], base + OFF_AHI + sw);
                LDSM4(al[mt], base + OFF_ALO + sw);
            }
            uint32_t bh[2][4], bl[2][4];
#pragma unroll
            for (int p = 0; p < 2; p++) {
                uint32_t off = (uint32_t)((Cb + 16 * p + bnoff) * 128 + (ks * 16 + bkoff) * 2);
                uint32_t sw = SWZ(off);
                LDSM4(bh[p], base + OFF_BHI + sw);
                LDSM4(bl[p], base + OFF_BLO + sw);
            }
#pragma unroll
            for (int mt = 0; mt < 2; mt++)
#pragma unroll
                for (int p = 0; p < 2; p++)
#pragma unroll
                    for (int q = 0; q < 2; q++) {
                        float* d = acc[mt][2 * p + q];
                        mma_bf16(d, ah[mt], bh[p][2 * q], bh[p][2 * q + 1]);
                        mma_bf16(d, ah[mt], bl[p][2 * q], bl[p][2 * q + 1]);
                        mma_bf16(d, al[mt], bh[p][2 * q], bh[p][2 * q + 1]);
                    }
        }
        __syncthreads();
    }

    // ---- stage e2 partials and p2
    float* e2p = smf + OFF_E2 / 4;
    float* p2s = smf + OFF_P2 / 4;
    float* wl  = smf + OFF_WL / 4;
    float* wa  = smf + OFF_WA / 4;
    e2p[t] = e2acc;
    if (t < CCLS) p2s[t] = g_p2[t];
    __syncthreads();

    // ---- logits into smf[0 .. 128*68)
    {
        int g  = lane >> 2;
        int tq = lane & 3;
#pragma unroll
        for (int mt = 0; mt < 2; mt++) {
            int r0 = Rb + 16 * mt + g;
            float e2a = e2p[2 * r0] + e2p[2 * r0 + 1];
            float e2b = e2p[2 * (r0 + 8)] + e2p[2 * (r0 + 8) + 1];
#pragma unroll
            for (int nt = 0; nt < 4; nt++) {
                int col = Cb + 8 * nt + 2 * tq;
                float p2a = p2s[col], p2b = p2s[col + 1];
                float* d = acc[mt][nt];
                float lg0 = -sqrtf(fmaxf(e2a + p2a - 2.f * d[0], 1e-12f));
                float lg1 = -sqrtf(fmaxf(e2a + p2b - 2.f * d[1], 1e-12f));
                float lg2 = -sqrtf(fmaxf(e2b + p2a - 2.f * d[2], 1e-12f));
                float lg3 = -sqrtf(fmaxf(e2b + p2b - 2.f * d[3], 1e-12f));
                *(float2*)&smf[r0 * 68 + col]       = make_float2(lg0, lg1);
                *(float2*)&smf[(r0 + 8) * 68 + col] = make_float2(lg2, lg3);
            }
        }
    }
    __syncthreads();

    // ---- per-row softmax / NLL / argmax; warp w rows w, w+8, ...
    float lossAcc = 0.f, accAcc = 0.f;
    for (int j = 0; j < 16; j++) {
        int lrow = wid + 8 * j;
        float v0 = smf[lrow * 68 + lane];
        float v1 = smf[lrow * 68 + 32 + lane];
        float bv; int bi;
        if (v1 > v0) { bv = v1; bi = lane + 32; } else { bv = v0; bi = lane; }
#pragma unroll
        for (int s = 16; s > 0; s >>= 1) {
            float ov = __shfl_xor_sync(0xffffffffu, bv, s);
            int   oi = __shfl_xor_sync(0xffffffffu, bi, s);
            if (ov > bv || (ov == bv && oi < bi)) { bv = ov; bi = oi; }
        }
        float e = expf(v0 - bv) + expf(v1 - bv);
#pragma unroll
        for (int s = 16; s > 0; s >>= 1)
            e += __shfl_xor_sync(0xffffffffu, e, s);
        float lse = bv + logf(e);
        int lab = labels[blk * 128 + lrow] & (CCLS - 1);
        float lv = smf[lrow * 68 + lab];
        lossAcc += (lse - lv);
        accAcc  += (bi == lab) ? 1.f : 0.f;
    }
    if (lane == 0) { wl[wid] = lossAcc; wa[wid] = accAcc; }
    __syncthreads();
    if (t == 0) {
        float L = 0.f, A = 0.f;
#pragma unroll
        for (int ww = 0; ww < 8; ww++) { L += wl[ww]; A += wa[ww]; }
        g_bl[blk] = L;
        g_ba[blk] = A;
    }
}

// ============================================================
// Kernel D: final reduce -> out[0]=loss, out[1]=accuracy
// ============================================================
__global__ void __launch_bounds__(512)
kD(float* __restrict__ out) {
    __shared__ float sl[512];
    __shared__ float sa[512];
    int t = threadIdx.x;
    sl[t] = g_bl[t];
    sa[t] = g_ba[t];
    __syncthreads();
    for (int s = 256; s >= 1; s >>= 1) {
        if (t < s) { sl[t] += sl[t + s]; sa[t] += sa[t + s]; }
        __syncthreads();
    }
    if (t == 0) {
        const float invN = 1.f / (float)NROWS;
        out[0] = sl[0] * invN;
        out[1] = sa[0] * invN;
    }
}

// ============================================================
extern "C" void kernel_launch(void* const* d_in, const int* in_sizes, int n_in,
                              void* d_out, int out_size) {
    const float* emb    = (const float*)d_in[0];
    const int*   labels = (const int*)d_in[1];
    float*       out    = (float*)d_out;

    const int smemA = (CCLS * DDIM + CCLS) * (int)sizeof(float) + 512 * (int)sizeof(int);
    cudaFuncSetAttribute(kA, cudaFuncAttributeMaxDynamicSharedMemorySize, smemA);
    cudaFuncSetAttribute(kC, cudaFuncAttributeMaxDynamicSharedMemorySize, SMC_BYTES);

    kA<<<GA, 256, smemA>>>(emb, labels);
    kB<<<CCLS, 512>>>();
    kC<<<GC, 256, SMC_BYTES>>>(emb, labels);
    kD<<<1, 512>>>(out);
}

// round 8
// speedup vs baseline: 1.0094x; 1.0094x over previous
#include <cuda_runtime.h>
#include <cuda_bf16.h>
#include <cstdint>
#include <math.h>

// Problem constants (fixed shapes)
#define NROWS 65536
#define DDIM  512
#define CCLS  64

#define GA 128                 // kernel A blocks
#define GC 512                 // kernel C blocks (128 rows each)

// ---------------- device scratch ----------------
__device__ float g_psums[GA * CCLS * DDIM];      // per-block partial class sums
__device__ float g_pcnt [GA * CCLS];             // per-block partial class counts
__device__ __nv_bfloat16 g_pHi[CCLS * DDIM];     // prototypes hi (bf16) [c][d]
__device__ __nv_bfloat16 g_pLo[CCLS * DDIM];     // prototypes lo (bf16)
__device__ float g_p2[CCLS];                     // ||p_c||^2 (fp32)
__device__ float g_bl[GC];                       // per-block loss partial
__device__ float g_ba[GC];                       // per-block accuracy partial

// ---------------- helpers ----------------
__device__ __forceinline__ uint32_t smem_u32(const void* p) {
    uint32_t a;
    asm("{ .reg .u64 t; cvta.to.shared.u64 t, %1; cvt.u32.u64 %0, t; }" : "=r"(a) : "l"(p));
    return a;
}
__device__ __forceinline__ uint32_t bf16x2_of(float lo, float hi) {
    uint32_t r;
    asm("cvt.rn.bf16x2.f32 %0, %1, %2;" : "=r"(r) : "f"(hi), "f"(lo));
    return r;
}
__device__ __forceinline__ float hf_lo(uint32_t h) { return __uint_as_float(h << 16); }
__device__ __forceinline__ float hf_hi(uint32_t h) { return __uint_as_float(h & 0xFFFF0000u); }

#define SWZ(off) ((off) ^ (((off) >> 3) & 0x70))

#define STS128(a, r0, r1, r2, r3) \
    asm volatile("st.shared.v4.b32 [%0], {%1,%2,%3,%4};" :: "r"(a), "r"(r0), "r"(r1), "r"(r2), "r"(r3) : "memory")

#define LDSM4(r, a) \
    asm volatile("ldmatrix.sync.aligned.m8n8.x4.shared.b16 {%0,%1,%2,%3}, [%4];" \
        : "=r"((r)[0]), "=r"((r)[1]), "=r"((r)[2]), "=r"((r)[3]) : "r"(a))

__device__ __forceinline__ void mma_bf16(float* d, const uint32_t* a, uint32_t b0, uint32_t b1) {
    asm volatile("mma.sync.aligned.m16n8k16.row.col.f32.bf16.bf16.f32 "
        "{%0,%1,%2,%3}, {%4,%5,%6,%7}, {%8,%9}, {%0,%1,%2,%3};"
        : "+f"(d[0]), "+f"(d[1]), "+f"(d[2]), "+f"(d[3])
        : "r"(a[0]), "r"(a[1]), "r"(a[2]), "r"(a[3]), "r"(b0), "r"(b1));
}

// ============================================================
// Kernel A: per-block segment sums (race-free column slices)
// ============================================================
__global__ void __launch_bounds__(256)
kA(const float* __restrict__ emb, const int* __restrict__ labels) {
    extern __shared__ float s[];
    float* acc  = s;
    float* cnt  = s + CCLS * DDIM;
    int*   slab = (int*)(s + CCLS * DDIM + CCLS);

    int t = threadIdx.x;
    int base = blockIdx.x * 512;

    for (int i = t * 4; i < CCLS * DDIM; i += 256 * 4)
        *(float4*)(acc + i) = make_float4(0.f, 0.f, 0.f, 0.f);
    if (t < CCLS) cnt[t] = 0.f;
    slab[t]       = labels[base + t] & (CCLS - 1);
    slab[t + 256] = labels[base + t + 256] & (CCLS - 1);
    __syncthreads();

    atomicAdd(&cnt[slab[t]], 1.f);
    atomicAdd(&cnt[slab[t + 256]], 1.f);

    const float* eBase = emb + (size_t)base * DDIM + t * 2;
#pragma unroll 4
    for (int r = 0; r < 512; r++) {
        float2 v = *(const float2*)(eBase + (size_t)r * DDIM);
        int l = slab[r];
        float2* a = (float2*)(acc + l * DDIM + t * 2);
        float2 c = *a;
        c.x += v.x; c.y += v.y;
        *a = c;
    }
    __syncthreads();

    float* out = g_psums + (size_t)blockIdx.x * (CCLS * DDIM);
    for (int i = t * 4; i < CCLS * DDIM; i += 256 * 4)
        *(float4*)(out + i) = *(float4*)(acc + i);
    if (t < CCLS) g_pcnt[blockIdx.x * CCLS + t] = cnt[t];
}

// ============================================================
// Kernel B: reduce partials -> prototypes (bf16 hi/lo) + p2
// ============================================================
__global__ void __launch_bounds__(512)
kB() {
    int c = blockIdx.x;
    int d = threadIdx.x;
    __shared__ float scnt[128];
    __shared__ float sred[512];

    if (d < 128) scnt[d] = g_pcnt[d * CCLS + c];
    __syncthreads();
    for (int s = 64; s >= 1; s >>= 1) {
        if (d < s) scnt[d] += scnt[d + s];
        __syncthreads();
    }
    float cnt = scnt[0];

    float sum = 0.f;
    const float* base = g_psums + (size_t)c * DDIM + d;
#pragma unroll 8
    for (int g = 0; g < GA; g++) sum += base[(size_t)g * (CCLS * DDIM)];
    float proto = sum / cnt;

    __nv_bfloat16 h = __float2bfloat16(proto);
    float hf = __bfloat162float(h);
    g_pHi[c * DDIM + d] = h;
    g_pLo[c * DDIM + d] = __float2bfloat16(proto - hf);

    sred[d] = proto * proto;
    __syncthreads();
    for (int s = 256; s >= 1; s >>= 1) {
        if (d < s) sred[d] += sred[d + s];
        __syncthreads();
    }
    if (d == 0) g_p2[c] = sred[0];
}

// ============================================================
// Kernel C: HMMA (mma.sync bf16 hi/lo) GEMM 128x64 per CTA over
//           K=512 in 8 chunks + fused softmax/NLL/argmax
// ============================================================
// smem byte offsets (from 1024-aligned base):
#define OFF_AHI   0            // 128x64 bf16 = 16KB
#define OFF_ALO   16384
#define OFF_BHI   32768        // 64x64 bf16 = 8KB
#define OFF_BLO   40960
//   stage total 49152; logits [128][68] f32 = 34816 reuses [0..)
#define OFF_LOG   0
#define OFF_E2    49152        // 256 floats (per (row,half) partials)
#define OFF_P2    50176        // 64 floats
#define OFF_WL    50432        // 8 floats
#define OFF_WA    50464        // 8 floats
#define SMC_BYTES (50496 + 1024)

__global__ void __launch_bounds__(256, 2)
kC(const float* __restrict__ emb, const int* __restrict__ labels) {
    extern __shared__ __align__(16) unsigned char smraw[];
    uint32_t raw = smem_u32(smraw);
    uint32_t base = (raw + 1023) & ~1023u;
    float* smf = (float*)(smraw + (base - raw));   // float view of aligned base

    const int t = threadIdx.x;
    const int wid = t >> 5, lane = t & 31;
    const int blk = blockIdx.x;

    const int Rb = (wid >> 1) * 32;   // warp row base (0..96)
    const int Cb = (wid & 1) * 32;    // warp col base (0 or 32)

    const int row  = t >> 1;          // 0..127 (A loader row)
    const int half = t & 1;           // 32-col half
    const float* aptr = emb + ((size_t)(blk * 128 + row)) * DDIM + half * 32;
    float e2acc = 0.f;

    float acc[2][4][4];
#pragma unroll
    for (int i = 0; i < 2; i++)
#pragma unroll
        for (int j = 0; j < 4; j++)
#pragma unroll
            for (int k = 0; k < 4; k++) acc[i][j][k] = 0.f;

    // per-lane ldmatrix offsets (constant across chunks except ks/k)
    const int arowoff = (lane & 7) + ((lane >> 3) & 1) * 8;
    const int akoff   = ((lane >> 4) & 1) * 8;
    const int bnoff   = (lane & 7) + ((lane >> 4) & 1) * 8;
    const int bkoff   = ((lane >> 3) & 1) * 8;

    for (int kt = 0; kt < 8; kt++) {
        // ---- A: load 32 f32, convert to bf16 hi/lo, swizzled STS
        float4 av[8];
#pragma unroll
        for (int i = 0; i < 8; i++) av[i] = *(const float4*)(aptr + kt * 64 + i * 4);
        // ---- B: copy hi/lo chunk rows
        uint4 bhv[2], blv[2];
#pragma unroll
        for (int i = 0; i < 2; i++) {
            int chunk = t * 2 + i;          // 0..511
            int brow = chunk >> 3;          // class 0..63
            int bcg  = chunk & 7;           // 16B chunk in 128B row
            size_t go = (size_t)brow * DDIM + kt * 64 + bcg * 8;
            bhv[i] = *(const uint4*)(g_pHi + go);
            blv[i] = *(const uint4*)(g_pLo + go);
        }

#pragma unroll
        for (int j = 0; j < 4; j++) {
            float4 v0 = av[2 * j], v1 = av[2 * j + 1];
            e2acc += v0.x * v0.x + v0.y * v0.y + v0.z * v0.z + v0.w * v0.w
                   + v1.x * v1.x + v1.y * v1.y + v1.z * v1.z + v1.w * v1.w;
            uint32_t h0 = bf16x2_of(v0.x, v0.y);
            uint32_t h1 = bf16x2_of(v0.z, v0.w);
            uint32_t h2 = bf16x2_of(v1.x, v1.y);
            uint32_t h3 = bf16x2_of(v1.z, v1.w);
            uint32_t l0 = bf16x2_of(v0.x - hf_lo(h0), v0.y - hf_hi(h0));
            uint32_t l1 = bf16x2_of(v0.z - hf_lo(h1), v0.w - hf_hi(h1));
            uint32_t l2 = bf16x2_of(v1.x - hf_lo(h2), v1.y - hf_hi(h2));
            uint32_t l3 = bf16x2_of(v1.z - hf_lo(h3), v1.w - hf_hi(h3));
            uint32_t boff = (uint32_t)(row * 128 + half * 64 + j * 16);
            uint32_t sw = SWZ(boff);
            STS128(base + OFF_AHI + sw, h0, h1, h2, h3);
            STS128(base + OFF_ALO + sw, l0, l1, l2, l3);
        }
#pragma unroll
        for (int i = 0; i < 2; i++) {
            int chunk = t * 2 + i;
            int brow = chunk >> 3, bcg = chunk & 7;
            uint32_t sw = SWZ((uint32_t)(brow * 128 + bcg * 16));
            STS128(base + OFF_BHI + sw, bhv[i].x, bhv[i].y, bhv[i].z, bhv[i].w);
            STS128(base + OFF_BLO + sw, blv[i].x, blv[i].y, blv[i].z, blv[i].w);
        }
        __syncthreads();

        // ---- compute: 4 k16 steps
#pragma unroll
        for (int ks = 0; ks < 4; ks++) {
            uint32_t ah[2][4], al[2][4];
#pragma unroll
            for (int mt = 0; mt < 2; mt++) {
                uint32_t off = (uint32_t)((Rb + 16 * mt + arowoff) * 128 + (ks * 16 + akoff) * 2);
                uint32_t sw = SWZ(off);
                LDSM4(ah[mt], base + OFF_AHI + sw);
                LDSM4(al[mt], base + OFF_ALO + sw);
            }
            uint32_t bh[2][4], bl[2][4];
#pragma unroll
            for (int p = 0; p < 2; p++) {
                uint32_t off = (uint32_t)((Cb + 16 * p + bnoff) * 128 + (ks * 16 + bkoff) * 2);
                uint32_t sw = SWZ(off);
                LDSM4(bh[p], base + OFF_BHI + sw);
                LDSM4(bl[p], base + OFF_BLO + sw);
            }
#pragma unroll
            for (int mt = 0; mt < 2; mt++)
#pragma unroll
                for (int p = 0; p < 2; p++)
#pragma unroll
                    for (int q = 0; q < 2; q++) {
                        float* d = acc[mt][2 * p + q];
                        mma_bf16(d, ah[mt], bh[p][2 * q], bh[p][2 * q + 1]);
                        mma_bf16(d, ah[mt], bl[p][2 * q], bl[p][2 * q + 1]);
                        mma_bf16(d, al[mt], bh[p][2 * q], bh[p][2 * q + 1]);
                    }
        }
        __syncthreads();
    }

    // ---- stage e2 partials and p2
    float* e2p = smf + OFF_E2 / 4;
    float* p2s = smf + OFF_P2 / 4;
    float* wl  = smf + OFF_WL / 4;
    float* wa  = smf + OFF_WA / 4;
    e2p[t] = e2acc;
    if (t < CCLS) p2s[t] = g_p2[t];
    __syncthreads();

    // ---- logits into smf[0 .. 128*68)
    {
        int g  = lane >> 2;
        int tq = lane & 3;
#pragma unroll
        for (int mt = 0; mt < 2; mt++) {
            int r0 = Rb + 16 * mt + g;
            float e2a = e2p[2 * r0] + e2p[2 * r0 + 1];
            float e2b = e2p[2 * (r0 + 8)] + e2p[2 * (r0 + 8) + 1];
#pragma unroll
            for (int nt = 0; nt < 4; nt++) {
                int col = Cb + 8 * nt + 2 * tq;
                float p2a = p2s[col], p2b = p2s[col + 1];
                float* d = acc[mt][nt];
                float lg0 = -sqrtf(fmaxf(e2a + p2a - 2.f * d[0], 1e-12f));
                float lg1 = -sqrtf(fmaxf(e2a + p2b - 2.f * d[1], 1e-12f));
                float lg2 = -sqrtf(fmaxf(e2b + p2a - 2.f * d[2], 1e-12f));
                float lg3 = -sqrtf(fmaxf(e2b + p2b - 2.f * d[3], 1e-12f));
                *(float2*)&smf[r0 * 68 + col]       = make_float2(lg0, lg1);
                *(float2*)&smf[(r0 + 8) * 68 + col] = make_float2(lg2, lg3);
            }
        }
    }
    __syncthreads();

    // ---- per-row softmax / NLL / argmax; warp w rows w, w+8, ...
    float lossAcc = 0.f, accAcc = 0.f;
    for (int j = 0; j < 16; j++) {
        int lrow = wid + 8 * j;
        float v0 = smf[lrow * 68 + lane];
        float v1 = smf[lrow * 68 + 32 + lane];
        float bv; int bi;
        if (v1 > v0) { bv = v1; bi = lane + 32; } else { bv = v0; bi = lane; }
#pragma unroll
        for (int s = 16; s > 0; s >>= 1) {
            float ov = __shfl_xor_sync(0xffffffffu, bv, s);
            int   oi = __shfl_xor_sync(0xffffffffu, bi, s);
            if (ov > bv || (ov == bv && oi < bi)) { bv = ov; bi = oi; }
        }
        float e = expf(v0 - bv) + expf(v1 - bv);
#pragma unroll
        for (int s = 16; s > 0; s >>= 1)
            e += __shfl_xor_sync(0xffffffffu, e, s);
        float lse = bv + logf(e);
        int lab = labels[blk * 128 + lrow] & (CCLS - 1);
        float lv = smf[lrow * 68 + lab];
        lossAcc += (lse - lv);
        accAcc  += (bi == lab) ? 1.f : 0.f;
    }
    if (lane == 0) { wl[wid] = lossAcc; wa[wid] = accAcc; }
    __syncthreads();
    if (t == 0) {
        float L = 0.f, A = 0.f;
#pragma unroll
        for (int ww = 0; ww < 8; ww++) { L += wl[ww]; A += wa[ww]; }
        g_bl[blk] = L;
        g_ba[blk] = A;
    }
}

// ============================================================
// Kernel D: final reduce -> out[0]=loss, out[1]=accuracy
// ============================================================
__global__ void __launch_bounds__(512)
kD(float* __restrict__ out) {
    __shared__ float sl[512];
    __shared__ float sa[512];
    int t = threadIdx.x;
    sl[t] = g_bl[t];
    sa[t] = g_ba[t];
    __syncthreads();
    for (int s = 256; s >= 1; s >>= 1) {
        if (t < s) { sl[t] += sl[t + s]; sa[t] += sa[t + s]; }
        __syncthreads();
    }
    if (t == 0) {
        const float invN = 1.f / (float)NROWS;
        out[0] = sl[0] * invN;
        out[1] = sa[0] * invN;
    }
}

// ============================================================
extern "C" void kernel_launch(void* const* d_in, const int* in_sizes, int n_in,
                              void* d_out, int out_size) {
    const float* emb    = (const float*)d_in[0];
    const int*   labels = (const int*)d_in[1];
    float*       out    = (float*)d_out;

    const int smemA = (CCLS * DDIM + CCLS) * (int)sizeof(float) + 512 * (int)sizeof(int);
    cudaFuncSetAttribute(kA, cudaFuncAttributeMaxDynamicSharedMemorySize, smemA);
    cudaFuncSetAttribute(kC, cudaFuncAttributeMaxDynamicSharedMemorySize, SMC_BYTES);

    kA<<<GA, 256, smemA>>>(emb, labels);
    kB<<<CCLS, 512>>>();
    kC<<<GC, 256, SMC_BYTES>>>(emb, labels);
    kD<<<1, 512>>>(out);
}

// round 9
// speedup vs baseline: 1.0609x; 1.0510x over previous
#include <cuda_runtime.h>
#include <cuda_bf16.h>
#include <cstdint>
#include <math.h>

// Problem constants (fixed shapes)
#define NROWS 65536
#define DDIM  512
#define CCLS  64

#define GA 128                 // kernel A blocks
#define GC 512                 // kernel C blocks (128 rows each)

// ---------------- device scratch ----------------
__device__ float g_psums[GA * CCLS * DDIM];      // per-block partial class sums
__device__ float g_pcnt [GA * CCLS];             // per-block partial class counts
__device__ __nv_bfloat16 g_pHi[CCLS * DDIM];     // prototypes hi (bf16) [c][d]
__device__ __nv_bfloat16 g_pLo[CCLS * DDIM];     // prototypes lo (bf16)
__device__ float g_p2[CCLS];                     // ||p_c||^2 (fp32)
__device__ float g_bl[GC];                       // per-block loss partial
__device__ float g_ba[GC];                       // per-block accuracy partial
__device__ unsigned int g_ctr;                   // kC completion counter

// ---------------- helpers ----------------
__device__ __forceinline__ uint32_t smem_u32(const void* p) {
    uint32_t a;
    asm("{ .reg .u64 t; cvta.to.shared.u64 t, %1; cvt.u32.u64 %0, t; }" : "=r"(a) : "l"(p));
    return a;
}
__device__ __forceinline__ uint32_t bf16x2_of(float lo, float hi) {
    uint32_t r;
    asm("cvt.rn.bf16x2.f32 %0, %1, %2;" : "=r"(r) : "f"(hi), "f"(lo));
    return r;
}
__device__ __forceinline__ float hf_lo(uint32_t h) { return __uint_as_float(h << 16); }
__device__ __forceinline__ float hf_hi(uint32_t h) { return __uint_as_float(h & 0xFFFF0000u); }

#define SWZ(off) ((off) ^ (((off) >> 3) & 0x70))

#define STS128(a, r0, r1, r2, r3) \
    asm volatile("st.shared.v4.b32 [%0], {%1,%2,%3,%4};" :: "r"(a), "r"(r0), "r"(r1), "r"(r2), "r"(r3) : "memory")

#define CP_ASYNC16(sa, ga) \
    asm volatile("cp.async.cg.shared.global [%0], [%1], 16;" :: "r"(sa), "l"(ga) : "memory")
#define CP_COMMIT() asm volatile("cp.async.commit_group;" ::: "memory")
#define CP_WAIT0()  asm volatile("cp.async.wait_group 0;" ::: "memory")

#define LDSM4(r, a) \
    asm volatile("ldmatrix.sync.aligned.m8n8.x4.shared.b16 {%0,%1,%2,%3}, [%4];" \
        : "=r"((r)[0]), "=r"((r)[1]), "=r"((r)[2]), "=r"((r)[3]) : "r"(a))

__device__ __forceinline__ void mma_bf16(float* d, const uint32_t* a, uint32_t b0, uint32_t b1) {
    asm volatile("mma.sync.aligned.m16n8k16.row.col.f32.bf16.bf16.f32 "
        "{%0,%1,%2,%3}, {%4,%5,%6,%7}, {%8,%9}, {%0,%1,%2,%3};"
        : "+f"(d[0]), "+f"(d[1]), "+f"(d[2]), "+f"(d[3])
        : "r"(a[0]), "r"(a[1]), "r"(a[2]), "r"(a[3]), "r"(b0), "r"(b1));
}

// ============================================================
// Kernel Z: reset completion counter (also shifts ncu -s slot)
// ============================================================
__global__ void kZ() { g_ctr = 0u; }

// ============================================================
// Kernel A: per-block segment sums (race-free column slices),
//           depth-2 software-pipelined global loads.
// ============================================================
__global__ void __launch_bounds__(256)
kA(const float* __restrict__ emb, const int* __restrict__ labels) {
    extern __shared__ float s[];
    float* acc  = s;
    float* cnt  = s + CCLS * DDIM;
    int*   slab = (int*)(s + CCLS * DDIM + CCLS);

    int t = threadIdx.x;
    int base = blockIdx.x * 512;

    for (int i = t * 4; i < CCLS * DDIM; i += 256 * 4)
        *(float4*)(acc + i) = make_float4(0.f, 0.f, 0.f, 0.f);
    if (t < CCLS) cnt[t] = 0.f;
    slab[t]       = labels[base + t] & (CCLS - 1);
    slab[t + 256] = labels[base + t + 256] & (CCLS - 1);
    __syncthreads();

    atomicAdd(&cnt[slab[t]], 1.f);
    atomicAdd(&cnt[slab[t + 256]], 1.f);

    const float* eBase = emb + (size_t)base * DDIM + t * 2;

    float2 buf[2][8];
#pragma unroll
    for (int i = 0; i < 8; i++) {
        buf[0][i] = *(const float2*)(eBase + (size_t)i * DDIM);
        buf[1][i] = *(const float2*)(eBase + (size_t)(8 + i) * DDIM);
    }
    for (int g = 0; g < 64; g++) {
        int cb = g & 1;
#pragma unroll
        for (int i = 0; i < 8; i++) {
            int l = slab[g * 8 + i];
            float2* a = (float2*)(acc + l * DDIM + t * 2);
            float2 c = *a;
            c.x += buf[cb][i].x; c.y += buf[cb][i].y;
            *a = c;
        }
        if (g + 2 < 64) {
#pragma unroll
            for (int i = 0; i < 8; i++)
                buf[cb][i] = *(const float2*)(eBase + (size_t)((g + 2) * 8 + i) * DDIM);
        }
    }
    __syncthreads();

    float* out = g_psums + (size_t)blockIdx.x * (CCLS * DDIM);
    for (int i = t * 4; i < CCLS * DDIM; i += 256 * 4)
        *(float4*)(out + i) = *(float4*)(acc + i);
    if (t < CCLS) g_pcnt[blockIdx.x * CCLS + t] = cnt[t];
}

// ============================================================
// Kernel B: reduce partials -> prototypes (bf16 hi/lo) + p2
// ============================================================
__global__ void __launch_bounds__(512)
kB() {
    int c = blockIdx.x;
    int d = threadIdx.x;
    __shared__ float scnt[128];
    __shared__ float sred[512];

    if (d < 128) scnt[d] = g_pcnt[d * CCLS + c];
    __syncthreads();
    for (int s = 64; s >= 1; s >>= 1) {
        if (d < s) scnt[d] += scnt[d + s];
        __syncthreads();
    }
    float cnt = scnt[0];

    float sum = 0.f;
    const float* base = g_psums + (size_t)c * DDIM + d;
#pragma unroll 8
    for (int g = 0; g < GA; g++) sum += base[(size_t)g * (CCLS * DDIM)];
    float proto = sum / cnt;

    __nv_bfloat16 h = __float2bfloat16(proto);
    float hf = __bfloat162float(h);
    g_pHi[c * DDIM + d] = h;
    g_pLo[c * DDIM + d] = __float2bfloat16(proto - hf);

    sred[d] = proto * proto;
    __syncthreads();
    for (int s = 256; s >= 1; s >>= 1) {
        if (d < s) sred[d] += sred[d + s];
        __syncthreads();
    }
    if (d == 0) g_p2[c] = sred[0];
}

// ============================================================
// Kernel C: HMMA bf16 hi/lo GEMM 128x64 per CTA over K=512 in 8
//           chunks + fused softmax/NLL/argmax + last-block reduce
// ============================================================
#define OFF_AHI   0            // 128x64 bf16 = 16KB
#define OFF_ALO   16384
#define OFF_BHI   32768        // 64x64 bf16 = 8KB
#define OFF_BLO   40960
#define OFF_LOG   0            // logits reuse [0..34816)
#define OFF_E2    49152        // 256 floats
#define OFF_P2    50176        // 64 floats
#define OFF_WL    50432        // 8 floats
#define OFF_WA    50464        // 8 floats
#define SMC_BYTES (50496 + 1024)

__global__ void __launch_bounds__(256, 2)
kC(const float* __restrict__ emb, const int* __restrict__ labels,
   float* __restrict__ outp) {
    extern __shared__ __align__(16) unsigned char smraw[];
    uint32_t raw = smem_u32(smraw);
    uint32_t base = (raw + 1023) & ~1023u;
    float* smf = (float*)(smraw + (base - raw));

    const int t = threadIdx.x;
    const int wid = t >> 5, lane = t & 31;
    const int blk = blockIdx.x;

    const int Rb = (wid >> 1) * 32;
    const int Cb = (wid & 1) * 32;

    const int row  = t >> 1;
    const int half = t & 1;
    const float* aptr = emb + ((size_t)(blk * 128 + row)) * DDIM + half * 32;
    float e2acc = 0.f;

    float acc[2][4][4];
#pragma unroll
    for (int i = 0; i < 2; i++)
#pragma unroll
        for (int j = 0; j < 4; j++)
#pragma unroll
            for (int k = 0; k < 4; k++) acc[i][j][k] = 0.f;

    const int arowoff = (lane & 7) + ((lane >> 3) & 1) * 8;
    const int akoff   = ((lane >> 4) & 1) * 8;
    const int bnoff   = (lane & 7) + ((lane >> 4) & 1) * 8;
    const int bkoff   = ((lane >> 3) & 1) * 8;

    // B chunk geometry (constant across kt)
    const int chunk0 = t * 2;
    const int brow0 = chunk0 >> 3, bcg0 = chunk0 & 7;
    const int brow1 = (chunk0 + 1) >> 3, bcg1 = (chunk0 + 1) & 7;
    const uint32_t bsw0 = SWZ((uint32_t)(brow0 * 128 + bcg0 * 16));
    const uint32_t bsw1 = SWZ((uint32_t)(brow1 * 128 + bcg1 * 16));

    for (int kt = 0; kt < 8; kt++) {
        // ---- B: cp.async hi/lo (no registers, no LSU round-trip)
        {
            size_t go0 = (size_t)brow0 * DDIM + kt * 64 + bcg0 * 8;
            size_t go1 = (size_t)brow1 * DDIM + kt * 64 + bcg1 * 8;
            CP_ASYNC16(base + OFF_BHI + bsw0, (const void*)(g_pHi + go0));
            CP_ASYNC16(base + OFF_BHI + bsw1, (const void*)(g_pHi + go1));
            CP_ASYNC16(base + OFF_BLO + bsw0, (const void*)(g_pLo + go0));
            CP_ASYNC16(base + OFF_BLO + bsw1, (const void*)(g_pLo + go1));
            CP_COMMIT();
        }

        // ---- A: load 32 f32, convert to bf16 hi/lo, swizzled STS
        float4 av[8];
#pragma unroll
        for (int i = 0; i < 8; i++) av[i] = *(const float4*)(aptr + kt * 64 + i * 4);
#pragma unroll
        for (int j = 0; j < 4; j++) {
            float4 v0 = av[2 * j], v1 = av[2 * j + 1];
            e2acc += v0.x * v0.x + v0.y * v0.y + v0.z * v0.z + v0.w * v0.w
                   + v1.x * v1.x + v1.y * v1.y + v1.z * v1.z + v1.w * v1.w;
            uint32_t h0 = bf16x2_of(v0.x, v0.y);
            uint32_t h1 = bf16x2_of(v0.z, v0.w);
            uint32_t h2 = bf16x2_of(v1.x, v1.y);
            uint32_t h3 = bf16x2_of(v1.z, v1.w);
            uint32_t l0 = bf16x2_of(v0.x - hf_lo(h0), v0.y - hf_hi(h0));
            uint32_t l1 = bf16x2_of(v0.z - hf_lo(h1), v0.w - hf_hi(h1));
            uint32_t l2 = bf16x2_of(v1.x - hf_lo(h2), v1.y - hf_hi(h2));
            uint32_t l3 = bf16x2_of(v1.z - hf_lo(h3), v1.w - hf_hi(h3));
            uint32_t sw = SWZ((uint32_t)(row * 128 + half * 64 + j * 16));
            STS128(base + OFF_AHI + sw, h0, h1, h2, h3);
            STS128(base + OFF_ALO + sw, l0, l1, l2, l3);
        }
        CP_WAIT0();
        __syncthreads();

        // ---- compute: 4 k16 steps
#pragma unroll
        for (int ks = 0; ks < 4; ks++) {
            uint32_t ah[2][4], al[2][4];
#pragma unroll
            for (int mt = 0; mt < 2; mt++) {
                uint32_t sw = SWZ((uint32_t)((Rb + 16 * mt + arowoff) * 128 + (ks * 16 + akoff) * 2));
                LDSM4(ah[mt], base + OFF_AHI + sw);
                LDSM4(al[mt], base + OFF_ALO + sw);
            }
            uint32_t bh[2][4], bl[2][4];
#pragma unroll
            for (int p = 0; p < 2; p++) {
                uint32_t sw = SWZ((uint32_t)((Cb + 16 * p + bnoff) * 128 + (ks * 16 + bkoff) * 2));
                LDSM4(bh[p], base + OFF_BHI + sw);
                LDSM4(bl[p], base + OFF_BLO + sw);
            }
#pragma unroll
            for (int mt = 0; mt < 2; mt++)
#pragma unroll
                for (int p = 0; p < 2; p++)
#pragma unroll
                    for (int q = 0; q < 2; q++) {
                        float* d = acc[mt][2 * p + q];
                        mma_bf16(d, ah[mt], bh[p][2 * q], bh[p][2 * q + 1]);
                        mma_bf16(d, ah[mt], bl[p][2 * q], bl[p][2 * q + 1]);
                        mma_bf16(d, al[mt], bh[p][2 * q], bh[p][2 * q + 1]);
                    }
        }
        __syncthreads();
    }

    // ---- stage e2 partials and p2
    float* e2p = smf + OFF_E2 / 4;
    float* p2s = smf + OFF_P2 / 4;
    float* wl  = smf + OFF_WL / 4;
    float* wa  = smf + OFF_WA / 4;
    e2p[t] = e2acc;
    if (t < CCLS) p2s[t] = g_p2[t];
    __syncthreads();

    // ---- logits into smf[0 .. 128*68)
    {
        int g  = lane >> 2;
        int tq = lane & 3;
#pragma unroll
        for (int mt = 0; mt < 2; mt++) {
            int r0 = Rb + 16 * mt + g;
            float e2a = e2p[2 * r0] + e2p[2 * r0 + 1];
            float e2b = e2p[2 * (r0 + 8)] + e2p[2 * (r0 + 8) + 1];
#pragma unroll
            for (int nt = 0; nt < 4; nt++) {
                int col = Cb + 8 * nt + 2 * tq;
                float p2a = p2s[col], p2b = p2s[col + 1];
                float* d = acc[mt][nt];
                float lg0 = -sqrtf(fmaxf(e2a + p2a - 2.f * d[0], 1e-12f));
                float lg1 = -sqrtf(fmaxf(e2a + p2b - 2.f * d[1], 1e-12f));
                float lg2 = -sqrtf(fmaxf(e2b + p2a - 2.f * d[2], 1e-12f));
                float lg3 = -sqrtf(fmaxf(e2b + p2b - 2.f * d[3], 1e-12f));
                *(float2*)&smf[r0 * 68 + col]       = make_float2(lg0, lg1);
                *(float2*)&smf[(r0 + 8) * 68 + col] = make_float2(lg2, lg3);
            }
        }
    }
    __syncthreads();

    // ---- per-row softmax / NLL / argmax
    float lossAcc = 0.f, accAcc = 0.f;
    for (int j = 0; j < 16; j++) {
        int lrow = wid + 8 * j;
        float v0 = smf[lrow * 68 + lane];
        float v1 = smf[lrow * 68 + 32 + lane];
        float bv; int bi;
        if (v1 > v0) { bv = v1; bi = lane + 32; } else { bv = v0; bi = lane; }
#pragma unroll
        for (int s = 16; s > 0; s >>= 1) {
            float ov = __shfl_xor_sync(0xffffffffu, bv, s);
            int   oi = __shfl_xor_sync(0xffffffffu, bi, s);
            if (ov > bv || (ov == bv && oi < bi)) { bv = ov; bi = oi; }
        }
        float e = expf(v0 - bv) + expf(v1 - bv);
#pragma unroll
        for (int s = 16; s > 0; s >>= 1)
            e += __shfl_xor_sync(0xffffffffu, e, s);
        float lse = bv + logf(e);
        int lab = labels[blk * 128 + lrow] & (CCLS - 1);
        float lv = smf[lrow * 68 + lab];
        lossAcc += (lse - lv);
        accAcc  += (bi == lab) ? 1.f : 0.f;
    }
    if (lane == 0) { wl[wid] = lossAcc; wa[wid] = accAcc; }
    __syncthreads();

    __shared__ unsigned int sLast;
    if (t == 0) {
        float L = 0.f, A = 0.f;
#pragma unroll
        for (int ww = 0; ww < 8; ww++) { L += wl[ww]; A += wa[ww]; }
        g_bl[blk] = L;
        g_ba[blk] = A;
        __threadfence();
        unsigned int v = atomicAdd(&g_ctr, 1u);
        sLast = (v == GC - 1) ? 1u : 0u;
    }
    __syncthreads();

    // ---- last finishing block: deterministic final reduce
    if (sLast) {
        float* rl = smf;          // reuse logits area
        float* ra = smf + 512;
        float l = __ldcg(&g_bl[t]) + __ldcg(&g_bl[t + 256]);
        float a = __ldcg(&g_ba[t]) + __ldcg(&g_ba[t + 256]);
        rl[t] = l; ra[t] = a;
        __syncthreads();
        for (int s = 128; s >= 1; s >>= 1) {
            if (t < s) { rl[t] += rl[t + s]; ra[t] += ra[t + s]; }
            __syncthreads();
        }
        if (t == 0) {
            const float invN = 1.f / (float)NROWS;
            outp[0] = rl[0] * invN;
            outp[1] = ra[0] * invN;
        }
    }
}

// ============================================================
extern "C" void kernel_launch(void* const* d_in, const int* in_sizes, int n_in,
                              void* d_out, int out_size) {
    const float* emb    = (const float*)d_in[0];
    const int*   labels = (const int*)d_in[1];
    float*       out    = (float*)d_out;

    const int smemA = (CCLS * DDIM + CCLS) * (int)sizeof(float) + 512 * (int)sizeof(int);
    cudaFuncSetAttribute(kA, cudaFuncAttributeMaxDynamicSharedMemorySize, smemA);
    cudaFuncSetAttribute(kC, cudaFuncAttributeMaxDynamicSharedMemorySize, SMC_BYTES);

    kZ<<<1, 1>>>();
    kA<<<GA, 256, smemA>>>(emb, labels);
    kB<<<CCLS, 512>>>();
    kC<<<GC, 256, SMC_BYTES>>>(emb, labels, out);
}

// round 14
// speedup vs baseline: 1.2226x; 1.1524x over previous
#include <cuda_runtime.h>
#include <cuda_bf16.h>
#include <cstdint>
#include <math.h>

// Problem constants (fixed shapes)
#define NROWS 65536
#define DDIM  512
#define CCLS  64

#define GA 128                 // kernel A blocks
#define GC 512                 // kernel C blocks (128 rows each)

// ---------------- device scratch ----------------
__device__ float g_psums[GA * CCLS * DDIM];      // per-block partial class sums
__device__ float g_pcnt [GA * CCLS];             // per-block partial class counts
__device__ __nv_bfloat16 g_pHi[CCLS * DDIM];     // prototypes hi (bf16) [c][d]
__device__ __nv_bfloat16 g_pLo[CCLS * DDIM];     // prototypes lo (bf16)
__device__ float g_p2[CCLS];                     // ||p_c||^2 (fp32)
__device__ float g_bl[GC];                       // per-block loss partial
__device__ float g_ba[GC];                       // per-block accuracy partial
__device__ unsigned int g_ctr;                   // kC completion counter

// ---------------- helpers ----------------
__device__ __forceinline__ uint32_t smem_u32(const void* p) {
    uint32_t a;
    asm("{ .reg .u64 t; cvta.to.shared.u64 t, %1; cvt.u32.u64 %0, t; }" : "=r"(a) : "l"(p));
    return a;
}
__device__ __forceinline__ uint32_t bf16x2_of(float lo, float hi) {
    uint32_t r;
    asm("cvt.rn.bf16x2.f32 %0, %1, %2;" : "=r"(r) : "f"(hi), "f"(lo));
    return r;
}
__device__ __forceinline__ float hf_lo(uint32_t h) { return __uint_as_float(h << 16); }
__device__ __forceinline__ float hf_hi(uint32_t h) { return __uint_as_float(h & 0xFFFF0000u); }

#define SWZ(off) ((off) ^ (((off) >> 3) & 0x70))

#define STS128(a, r0, r1, r2, r3) \
    asm volatile("st.shared.v4.b32 [%0], {%1,%2,%3,%4};" :: "r"(a), "r"(r0), "r"(r1), "r"(r2), "r"(r3) : "memory")

#define CP_ASYNC16(sa, ga) \
    asm volatile("cp.async.cg.shared.global [%0], [%1], 16;" :: "r"(sa), "l"(ga) : "memory")
#define CP_COMMIT() asm volatile("cp.async.commit_group;" ::: "memory")
#define CP_WAIT0()  asm volatile("cp.async.wait_group 0;" ::: "memory")

#define LDSM4(r, a) \
    asm volatile("ldmatrix.sync.aligned.m8n8.x4.shared.b16 {%0,%1,%2,%3}, [%4];" \
        : "=r"((r)[0]), "=r"((r)[1]), "=r"((r)[2]), "=r"((r)[3]) : "r"(a))

__device__ __forceinline__ void mma_bf16(float* d, const uint32_t* a, uint32_t b0, uint32_t b1) {
    asm volatile("mma.sync.aligned.m16n8k16.row.col.f32.bf16.bf16.f32 "
        "{%0,%1,%2,%3}, {%4,%5,%6,%7}, {%8,%9}, {%0,%1,%2,%3};"
        : "+f"(d[0]), "+f"(d[1]), "+f"(d[2]), "+f"(d[3])
        : "r"(a[0]), "r"(a[1]), "r"(a[2]), "r"(a[3]), "r"(b0), "r"(b1));
}

// ============================================================
// Kernel Z: reset completion counter
// ============================================================
__global__ void kZ() { g_ctr = 0u; }

// ============================================================
// Kernel A: per-block segment sums. 512 threads, 1 f32 column
// per thread (conflict-free), depth-8 row prefetch.
// ============================================================
__global__ void __launch_bounds__(512)
kA(const float* __restrict__ emb, const int* __restrict__ labels) {
    extern __shared__ float s[];
    float* acc  = s;
    float* cnt  = s + CCLS * DDIM;
    int*   slab = (int*)(s + CCLS * DDIM + CCLS);

    int t = threadIdx.x;
    int base = blockIdx.x * 512;

    for (int i = t * 4; i < CCLS * DDIM; i += 512 * 4)
        *(float4*)(acc + i) = make_float4(0.f, 0.f, 0.f, 0.f);
    if (t < CCLS) cnt[t] = 0.f;
    slab[t] = labels[base + t] & (CCLS - 1);
    __syncthreads();

    atomicAdd(&cnt[slab[t]], 1.f);

    const float* eBase = emb + (size_t)base * DDIM + t;
    float cur[8], nxt[8];
#pragma unroll
    for (int i = 0; i < 8; i++) cur[i] = eBase[(size_t)i * DDIM];

    for (int g = 0; g < 64; g++) {
        if (g < 63) {
#pragma unroll
            for (int i = 0; i < 8; i++)
                nxt[i] = eBase[(size_t)((g + 1) * 8 + i) * DDIM];
        }
#pragma unroll
        for (int i = 0; i < 8; i++)
            acc[slab[g * 8 + i] * DDIM + t] += cur[i];
#pragma unroll
        for (int i = 0; i < 8; i++) cur[i] = nxt[i];
    }
    __syncthreads();

    float* out = g_psums + (size_t)blockIdx.x * (CCLS * DDIM);
    for (int i = t * 4; i < CCLS * DDIM; i += 512 * 4)
        *(float4*)(out + i) = *(float4*)(acc + i);
    if (t < CCLS) g_pcnt[blockIdx.x * CCLS + t] = cnt[t];
}

// ============================================================
// Kernel B: reduce partials -> prototypes (bf16 hi/lo) + p2
// ============================================================
__global__ void __launch_bounds__(512)
kB() {
    int c = blockIdx.x;
    int d = threadIdx.x;
    __shared__ float scnt[128];
    __shared__ float sred[512];

    if (d < 128) scnt[d] = g_pcnt[d * CCLS + c];
    __syncthreads();
    for (int s = 64; s >= 1; s >>= 1) {
        if (d < s) scnt[d] += scnt[d + s];
        __syncthreads();
    }
    float cnt = scnt[0];

    float sum = 0.f;
    const float* base = g_psums + (size_t)c * DDIM + d;
#pragma unroll 8
    for (int g = 0; g < GA; g++) sum += base[(size_t)g * (CCLS * DDIM)];
    float proto = sum / cnt;

    __nv_bfloat16 h = __float2bfloat16(proto);
    float hf = __bfloat162float(h);
    g_pHi[c * DDIM + d] = h;
    g_pLo[c * DDIM + d] = __float2bfloat16(proto - hf);

    sred[d] = proto * proto;
    __syncthreads();
    for (int s = 256; s >= 1; s >>= 1) {
        if (d < s) sred[d] += sred[d + s];
        __syncthreads();
    }
    if (d == 0) g_p2[c] = sred[0];
}

// ============================================================
// Kernel C: HMMA bf16 hi/lo GEMM 128x64 per CTA over K=512,
//           DOUBLE-BUFFERED, + fused softmax/NLL/argmax +
//           last-block final reduce
// ============================================================
#define BUFSZ     49152
#define OFF_AHI(b) ((b) * BUFSZ)
#define OFF_ALO(b) ((b) * BUFSZ + 16384)
#define OFF_BHI(b) ((b) * BUFSZ + 32768)
#define OFF_BLO(b) ((b) * BUFSZ + 40960)
#define OFF_E2    98304        // 256 floats
#define OFF_P2    99328        // 64 floats
#define OFF_WL    99584        // 8 floats
#define OFF_WA    99616        // 8 floats
#define SMC_BYTES (99648 + 1024)

__global__ void __launch_bounds__(256, 2)
kC(const float* __restrict__ emb, const int* __restrict__ labels,
   float* __restrict__ outp) {
    extern __shared__ __align__(16) unsigned char smraw[];
    uint32_t raw = smem_u32(smraw);
    uint32_t base = (raw + 1023) & ~1023u;
    float* smf = (float*)(smraw + (base - raw));

    const int t = threadIdx.x;
    const int wid = t >> 5, lane = t & 31;
    const int blk = blockIdx.x;

    const int Rb = (wid >> 1) * 32;
    const int Cb = (wid & 1) * 32;

    const int row  = t >> 1;
    const int half = t & 1;
    const float* aptr = emb + ((size_t)(blk * 128 + row)) * DDIM + half * 32;
    float e2acc = 0.f;

    float acc[2][4][4];
#pragma unroll
    for (int i = 0; i < 2; i++)
#pragma unroll
        for (int j = 0; j < 4; j++)
#pragma unroll
            for (int k = 0; k < 4; k++) acc[i][j][k] = 0.f;

    const int arowoff = (lane & 7) + ((lane >> 3) & 1) * 8;
    const int akoff   = ((lane >> 4) & 1) * 8;
    const int bnoff   = (lane & 7) + ((lane >> 4) & 1) * 8;
    const int bkoff   = ((lane >> 3) & 1) * 8;

    // B chunk geometry (constant across kt)
    const int chunk0 = t * 2;
    const int brow0 = chunk0 >> 3, bcg0 = chunk0 & 7;
    const int brow1 = (chunk0 + 1) >> 3, bcg1 = (chunk0 + 1) & 7;
    const uint32_t bsw0 = SWZ((uint32_t)(brow0 * 128 + bcg0 * 16));
    const uint32_t bsw1 = SWZ((uint32_t)(brow1 * 128 + bcg1 * 16));
    const uint32_t asw[4] = {
        SWZ((uint32_t)(row * 128 + half * 64 + 0)),
        SWZ((uint32_t)(row * 128 + half * 64 + 16)),
        SWZ((uint32_t)(row * 128 + half * 64 + 32)),
        SWZ((uint32_t)(row * 128 + half * 64 + 48))
    };

    // ---- prologue: stage tile 0 into buffer 0
    {
        size_t go0 = (size_t)brow0 * DDIM + bcg0 * 8;
        size_t go1 = (size_t)brow1 * DDIM + bcg1 * 8;
        CP_ASYNC16(base + OFF_BHI(0) + bsw0, (const void*)(g_pHi + go0));
        CP_ASYNC16(base + OFF_BHI(0) + bsw1, (const void*)(g_pHi + go1));
        CP_ASYNC16(base + OFF_BLO(0) + bsw0, (const void*)(g_pLo + go0));
        CP_ASYNC16(base + OFF_BLO(0) + bsw1, (const void*)(g_pLo + go1));
        CP_COMMIT();
        float4 av[8];
#pragma unroll
        for (int i = 0; i < 8; i++) av[i] = *(const float4*)(aptr + i * 4);
#pragma unroll
        for (int j = 0; j < 4; j++) {
            float4 v0 = av[2 * j], v1 = av[2 * j + 1];
            e2acc += v0.x * v0.x + v0.y * v0.y + v0.z * v0.z + v0.w * v0.w
                   + v1.x * v1.x + v1.y * v1.y + v1.z * v1.z + v1.w * v1.w;
            uint32_t h0 = bf16x2_of(v0.x, v0.y);
            uint32_t h1 = bf16x2_of(v0.z, v0.w);
            uint32_t h2 = bf16x2_of(v1.x, v1.y);
            uint32_t h3 = bf16x2_of(v1.z, v1.w);
            uint32_t l0 = bf16x2_of(v0.x - hf_lo(h0), v0.y - hf_hi(h0));
            uint32_t l1 = bf16x2_of(v0.z - hf_lo(h1), v0.w - hf_hi(h1));
            uint32_t l2 = bf16x2_of(v1.x - hf_lo(h2), v1.y - hf_hi(h2));
            uint32_t l3 = bf16x2_of(v1.z - hf_lo(h3), v1.w - hf_hi(h3));
            STS128(base + OFF_AHI(0) + asw[j], h0, h1, h2, h3);
            STS128(base + OFF_ALO(0) + asw[j], l0, l1, l2, l3);
        }
        CP_WAIT0();
        __syncthreads();
    }

    for (int kt = 0; kt < 8; kt++) {
        int cur = kt & 1, nxt = cur ^ 1;

        // ---- prefetch tile kt+1: LDG A into regs, cp.async B into nxt
        float4 av[8];
        if (kt < 7) {
            size_t go0 = (size_t)brow0 * DDIM + (kt + 1) * 64 + bcg0 * 8;
            size_t go1 = (size_t)brow1 * DDIM + (kt + 1) * 64 + bcg1 * 8;
            CP_ASYNC16(base + OFF_BHI(nxt) + bsw0, (const void*)(g_pHi + go0));
            CP_ASYNC16(base + OFF_BHI(nxt) + bsw1, (const void*)(g_pHi + go1));
            CP_ASYNC16(base + OFF_BLO(nxt) + bsw0, (const void*)(g_pLo + go0));
            CP_ASYNC16(base + OFF_BLO(nxt) + bsw1, (const void*)(g_pLo + go1));
            CP_COMMIT();
#pragma unroll
            for (int i = 0; i < 8; i++)
                av[i] = *(const float4*)(aptr + (kt + 1) * 64 + i * 4);
        }

        // ---- compute on buffer cur: 4 k16 steps
#pragma unroll
        for (int ks = 0; ks < 4; ks++) {
            uint32_t ah[2][4], al[2][4];
#pragma unroll
            for (int mt = 0; mt < 2; mt++) {
                uint32_t sw = SWZ((uint32_t)((Rb + 16 * mt + arowoff) * 128 + (ks * 16 + akoff) * 2));
                LDSM4(ah[mt], base + OFF_AHI(cur) + sw);
                LDSM4(al[mt], base + OFF_ALO(cur) + sw);
            }
            uint32_t bh[2][4], bl[2][4];
#pragma unroll
            for (int p = 0; p < 2; p++) {
                uint32_t sw = SWZ((uint32_t)((Cb + 16 * p + bnoff) * 128 + (ks * 16 + bkoff) * 2));
                LDSM4(bh[p], base + OFF_BHI(cur) + sw);
                LDSM4(bl[p], base + OFF_BLO(cur) + sw);
            }
#pragma unroll
            for (int mt = 0; mt < 2; mt++)
#pragma unroll
                for (int p = 0; p < 2; p++)
#pragma unroll
                    for (int q = 0; q < 2; q++) {
                        float* d = acc[mt][2 * p + q];
                        mma_bf16(d, ah[mt], bh[p][2 * q], bh[p][2 * q + 1]);
                        mma_bf16(d, ah[mt], bl[p][2 * q], bl[p][2 * q + 1]);
                        mma_bf16(d, al[mt], bh[p][2 * q], bh[p][2 * q + 1]);
                    }
        }

        // ---- convert + STS A(kt+1) into nxt
        if (kt < 7) {
#pragma unroll
            for (int j = 0; j < 4; j++) {
                float4 v0 = av[2 * j], v1 = av[2 * j + 1];
                e2acc += v0.x * v0.x + v0.y * v0.y + v0.z * v0.z + v0.w * v0.w
                       + v1.x * v1.x + v1.y * v1.y + v1.z * v1.z + v1.w * v1.w;
                uint32_t h0 = bf16x2_of(v0.x, v0.y);
                uint32_t h1 = bf16x2_of(v0.z, v0.w);
                uint32_t h2 = bf16x2_of(v1.x, v1.y);
                uint32_t h3 = bf16x2_of(v1.z, v1.w);
                uint32_t l0 = bf16x2_of(v0.x - hf_lo(h0), v0.y - hf_hi(h0));
                uint32_t l1 = bf16x2_of(v0.z - hf_lo(h1), v0.w - hf_hi(h1));
                uint32_t l2 = bf16x2_of(v1.x - hf_lo(h2), v1.y - hf_hi(h2));
                uint32_t l3 = bf16x2_of(v1.z - hf_lo(h3), v1.w - hf_hi(h3));
                STS128(base + OFF_AHI(nxt) + asw[j], h0, h1, h2, h3);
                STS128(base + OFF_ALO(nxt) + asw[j], l0, l1, l2, l3);
            }
            CP_WAIT0();
        }
        __syncthreads();
    }

    // ---- stage e2 partials and p2
    float* e2p = smf + OFF_E2 / 4;
    float* p2s = smf + OFF_P2 / 4;
    float* wl  = smf + OFF_WL / 4;
    float* wa  = smf + OFF_WA / 4;
    e2p[t] = e2acc;
    if (t < CCLS) p2s[t] = g_p2[t];
    __syncthreads();

    // ---- logits into smf[0 .. 128*68)
    {
        int g  = lane >> 2;
        int tq = lane & 3;
#pragma unroll
        for (int mt = 0; mt < 2; mt++) {
            int r0 = Rb + 16 * mt + g;
            float e2a = e2p[2 * r0] + e2p[2 * r0 + 1];
            float e2b = e2p[2 * (r0 + 8)] + e2p[2 * (r0 + 8) + 1];
#pragma unroll
            for (int nt = 0; nt < 4; nt++) {
                int col = Cb + 8 * nt + 2 * tq;
                float p2a = p2s[col], p2b = p2s[col + 1];
                float* d = acc[mt][nt];
                float lg0 = -sqrtf(fmaxf(e2a + p2a - 2.f * d[0], 1e-12f));
                float lg1 = -sqrtf(fmaxf(e2a + p2b - 2.f * d[1], 1e-12f));
                float lg2 = -sqrtf(fmaxf(e2b + p2a - 2.f * d[2], 1e-12f));
                float lg3 = -sqrtf(fmaxf(e2b + p2b - 2.f * d[3], 1e-12f));
                *(float2*)&smf[r0 * 68 + col]       = make_float2(lg0, lg1);
                *(float2*)&smf[(r0 + 8) * 68 + col] = make_float2(lg2, lg3);
            }
        }
    }
    __syncthreads();

    // ---- per-row softmax / NLL / argmax
    float lossAcc = 0.f, accAcc = 0.f;
    for (int j = 0; j < 16; j++) {
        int lrow = wid + 8 * j;
        float v0 = smf[lrow * 68 + lane];
        float v1 = smf[lrow * 68 + 32 + lane];
        float bv; int bi;
        if (v1 > v0) { bv = v1; bi = lane + 32; } else { bv = v0; bi = lane; }
#pragma unroll
        for (int s = 16; s > 0; s >>= 1) {
            float ov = __shfl_xor_sync(0xffffffffu, bv, s);
            int   oi = __shfl_xor_sync(0xffffffffu, bi, s);
            if (ov > bv || (ov == bv && oi < bi)) { bv = ov; bi = oi; }
        }
        float e = expf(v0 - bv) + expf(v1 - bv);
#pragma unroll
        for (int s = 16; s > 0; s >>= 1)
            e += __shfl_xor_sync(0xffffffffu, e, s);
        float lse = bv + logf(e);
        int lab = labels[blk * 128 + lrow] & (CCLS - 1);
        float lv = smf[lrow * 68 + lab];
        lossAcc += (lse - lv);
        accAcc  += (bi == lab) ? 1.f : 0.f;
    }
    if (lane == 0) { wl[wid] = lossAcc; wa[wid] = accAcc; }
    __syncthreads();

    __shared__ unsigned int sLast;
    if (t == 0) {
        float L = 0.f, A = 0.f;
#pragma unroll
        for (int ww = 0; ww < 8; ww++) { L += wl[ww]; A += wa[ww]; }
        g_bl[blk] = L;
        g_ba[blk] = A;
        __threadfence();
        unsigned int v = atomicAdd(&g_ctr, 1u);
        sLast = (v == GC - 1) ? 1u : 0u;
    }
    __syncthreads();

    if (sLast) {
        float* rl = smf;
        float* ra = smf + 512;
        float l = __ldcg(&g_bl[t]) + __ldcg(&g_bl[t + 256]);
        float a = __ldcg(&g_ba[t]) + __ldcg(&g_ba[t + 256]);
        rl[t] = l; ra[t] = a;
        __syncthreads();
        for (int s = 128; s >= 1; s >>= 1) {
            if (t < s) { rl[t] += rl[t + s]; ra[t] += ra[t + s]; }
            __syncthreads();
        }
        if (t == 0) {
            const float invN = 1.f / (float)NROWS;
            outp[0] = rl[0] * invN;
            outp[1] = ra[0] * invN;
        }
    }
}

// ============================================================
extern "C" void kernel_launch(void* const* d_in, const int* in_sizes, int n_in,
                              void* d_out, int out_size) {
    const float* emb    = (const float*)d_in[0];
    const int*   labels = (const int*)d_in[1];
    float*       out    = (float*)d_out;

    const int smemA = (CCLS * DDIM + CCLS) * (int)sizeof(float) + 512 * (int)sizeof(int);
    cudaFuncSetAttribute(kA, cudaFuncAttributeMaxDynamicSharedMemorySize, smemA);
    cudaFuncSetAttribute(kC, cudaFuncAttributeMaxDynamicSharedMemorySize, SMC_BYTES);

    kZ<<<1, 1>>>();
    kA<<<GA, 512, smemA>>>(emb, labels);
    kB<<<CCLS, 512>>>();
    kC<<<GC, 256, SMC_BYTES>>>(emb, labels, out);
}

// round 15
// speedup vs baseline: 1.4692x; 1.2017x over previous
#include <cuda_runtime.h>
#include <cuda_bf16.h>
#include <cstdint>
#include <math.h>

// Problem constants (fixed shapes)
#define NROWS 65536
#define DDIM  512
#define CCLS  64

#define GA 128                 // kernel A blocks
#define GC 512                 // kernel C blocks (128 rows each)

// ---------------- device scratch ----------------
__device__ float g_psums[GA * CCLS * DDIM];      // per-block partial class sums
__device__ float g_pcnt [GA * CCLS];             // per-block partial class counts
__device__ __nv_bfloat16 g_pHi[CCLS * DDIM];     // prototypes hi (bf16) [c][d]
__device__ __nv_bfloat16 g_pLo[CCLS * DDIM];     // prototypes lo (bf16)
__device__ float g_p2[CCLS];                     // ||p_c||^2 (fp32)
__device__ float g_bl[GC];                       // per-block loss partial
__device__ float g_ba[GC];                       // per-block accuracy partial
__device__ unsigned int g_ctr;                   // kC completion counter

// ---------------- helpers ----------------
__device__ __forceinline__ uint32_t smem_u32(const void* p) {
    uint32_t a;
    asm("{ .reg .u64 t; cvta.to.shared.u64 t, %1; cvt.u32.u64 %0, t; }" : "=r"(a) : "l"(p));
    return a;
}
__device__ __forceinline__ uint32_t bf16x2_of(float lo, float hi) {
    uint32_t r;
    asm("cvt.rn.bf16x2.f32 %0, %1, %2;" : "=r"(r) : "f"(hi), "f"(lo));
    return r;
}
__device__ __forceinline__ float hf_lo(uint32_t h) { return __uint_as_float(h << 16); }
__device__ __forceinline__ float hf_hi(uint32_t h) { return __uint_as_float(h & 0xFFFF0000u); }

#define SWZ(off) ((off) ^ (((off) >> 3) & 0x70))

#define STS64(a, r0, r1) \
    asm volatile("st.shared.v2.b32 [%0], {%1,%2};" :: "r"(a), "r"(r0), "r"(r1) : "memory")

#define CP_ASYNC16(sa, ga) \
    asm volatile("cp.async.cg.shared.global [%0], [%1], 16;" :: "r"(sa), "l"(ga) : "memory")
#define CP_COMMIT() asm volatile("cp.async.commit_group;" ::: "memory")
#define CP_WAIT0()  asm volatile("cp.async.wait_group 0;" ::: "memory")

#define LDSM4(r, a) \
    asm volatile("ldmatrix.sync.aligned.m8n8.x4.shared.b16 {%0,%1,%2,%3}, [%4];" \
        : "=r"((r)[0]), "=r"((r)[1]), "=r"((r)[2]), "=r"((r)[3]) : "r"(a))

__device__ __forceinline__ void mma_bf16(float* d, const uint32_t* a, uint32_t b0, uint32_t b1) {
    asm volatile("mma.sync.aligned.m16n8k16.row.col.f32.bf16.bf16.f32 "
        "{%0,%1,%2,%3}, {%4,%5,%6,%7}, {%8,%9}, {%0,%1,%2,%3};"
        : "+f"(d[0]), "+f"(d[1]), "+f"(d[2]), "+f"(d[3])
        : "r"(a[0]), "r"(a[1]), "r"(a[2]), "r"(a[3]), "r"(b0), "r"(b1));
}

// ============================================================
// Kernel Z: reset completion counter
// ============================================================
__global__ void kZ() { g_ctr = 0u; }

// ============================================================
// Kernel A: per-block segment sums. 512 threads, 1 f32 column
// per thread (conflict-free), depth-8 row prefetch.
// ============================================================
__global__ void __launch_bounds__(512)
kA(const float* __restrict__ emb, const int* __restrict__ labels) {
    extern __shared__ float s[];
    float* acc  = s;
    float* cnt  = s + CCLS * DDIM;
    int*   slab = (int*)(s + CCLS * DDIM + CCLS);

    int t = threadIdx.x;
    int base = blockIdx.x * 512;

    for (int i = t * 4; i < CCLS * DDIM; i += 512 * 4)
        *(float4*)(acc + i) = make_float4(0.f, 0.f, 0.f, 0.f);
    if (t < CCLS) cnt[t] = 0.f;
    slab[t] = labels[base + t] & (CCLS - 1);
    __syncthreads();

    atomicAdd(&cnt[slab[t]], 1.f);

    const float* eBase = emb + (size_t)base * DDIM + t;
    float cur[8], nxt[8];
#pragma unroll
    for (int i = 0; i < 8; i++) cur[i] = eBase[(size_t)i * DDIM];

    for (int g = 0; g < 64; g++) {
        if (g < 63) {
#pragma unroll
            for (int i = 0; i < 8; i++)
                nxt[i] = eBase[(size_t)((g + 1) * 8 + i) * DDIM];
        }
#pragma unroll
        for (int i = 0; i < 8; i++)
            acc[slab[g * 8 + i] * DDIM + t] += cur[i];
#pragma unroll
        for (int i = 0; i < 8; i++) cur[i] = nxt[i];
    }
    __syncthreads();

    float* out = g_psums + (size_t)blockIdx.x * (CCLS * DDIM);
    for (int i = t * 4; i < CCLS * DDIM; i += 512 * 4)
        *(float4*)(out + i) = *(float4*)(acc + i);
    if (t < CCLS) g_pcnt[blockIdx.x * CCLS + t] = cnt[t];
}

// ============================================================
// Kernel B: reduce partials -> prototypes (bf16 hi/lo) + p2
// ============================================================
__global__ void __launch_bounds__(512)
kB() {
    int c = blockIdx.x;
    int d = threadIdx.x;
    __shared__ float scnt[128];
    __shared__ float sred[512];

    if (d < 128) scnt[d] = g_pcnt[d * CCLS + c];
    __syncthreads();
    for (int s = 64; s >= 1; s >>= 1) {
        if (d < s) scnt[d] += scnt[d + s];
        __syncthreads();
    }
    float cnt = scnt[0];

    float sum = 0.f;
    const float* base = g_psums + (size_t)c * DDIM + d;
#pragma unroll 8
    for (int g = 0; g < GA; g++) sum += base[(size_t)g * (CCLS * DDIM)];
    float proto = sum / cnt;

    __nv_bfloat16 h = __float2bfloat16(proto);
    float hf = __bfloat162float(h);
    g_pHi[c * DDIM + d] = h;
    g_pLo[c * DDIM + d] = __float2bfloat16(proto - hf);

    sred[d] = proto * proto;
    __syncthreads();
    for (int s = 256; s >= 1; s >>= 1) {
        if (d < s) sred[d] += sred[d + s];
        __syncthreads();
    }
    if (d == 0) g_p2[c] = sred[0];
}

// ============================================================
// Kernel C: HMMA bf16 hi/lo GEMM 128x64 per CTA over K=512,
//           double-buffered, COALESCED A loads, fused epilogue
// ============================================================
#define BUFSZ     49152
#define OFF_AHI(b) ((b) * BUFSZ)
#define OFF_ALO(b) ((b) * BUFSZ + 16384)
#define OFF_BHI(b) ((b) * BUFSZ + 32768)
#define OFF_BLO(b) ((b) * BUFSZ + 40960)
#define OFF_E2    98304        // 128 floats (per-row e2)
#define OFF_P2    98816        // 64 floats
#define OFF_WL    99072        // 8 floats
#define OFF_WA    99104        // 8 floats
#define SMC_BYTES (99136 + 1024)

__global__ void __launch_bounds__(256, 2)
kC(const float* __restrict__ emb, const int* __restrict__ labels,
   float* __restrict__ outp) {
    extern __shared__ __align__(16) unsigned char smraw[];
    uint32_t raw = smem_u32(smraw);
    uint32_t base = (raw + 1023) & ~1023u;
    float* smf = (float*)(smraw + (base - raw));

    const int t = threadIdx.x;
    const int wid = t >> 5, lane = t & 31;
    const int blk = blockIdx.x;

    const int Rb = (wid >> 1) * 32;
    const int Cb = (wid & 1) * 32;

    // ---- coalesced A-loader mapping: round j -> row (t>>4)+16j,
    //      cols (t&15)*4 .. +3 within the kt-chunk of 64
    const int rg = t >> 4;            // 0..15
    const int lq = t & 15;            // 0..15
    const float* aRow = emb + ((size_t)(blk * 128 + rg)) * DDIM + lq * 4;
    float e2r[8];
#pragma unroll
    for (int j = 0; j < 8; j++) e2r[j] = 0.f;

    float acc[2][4][4];
#pragma unroll
    for (int i = 0; i < 2; i++)
#pragma unroll
        for (int j = 0; j < 4; j++)
#pragma unroll
            for (int k = 0; k < 4; k++) acc[i][j][k] = 0.f;

    const int arowoff = (lane & 7) + ((lane >> 3) & 1) * 8;
    const int akoff   = ((lane >> 4) & 1) * 8;
    const int bnoff   = (lane & 7) + ((lane >> 4) & 1) * 8;
    const int bkoff   = ((lane >> 3) & 1) * 8;

    // B chunk geometry (constant across kt)
    const int chunk0 = t * 2;
    const int brow0 = chunk0 >> 3, bcg0 = chunk0 & 7;
    const int brow1 = (chunk0 + 1) >> 3, bcg1 = (chunk0 + 1) & 7;
    const uint32_t bsw0 = SWZ((uint32_t)(brow0 * 128 + bcg0 * 16));
    const uint32_t bsw1 = SWZ((uint32_t)(brow1 * 128 + bcg1 * 16));

    // A STS offsets per round j (8B granular; SWZ only touches bits>=4)
    uint32_t aswj[8];
#pragma unroll
    for (int j = 0; j < 8; j++)
        aswj[j] = SWZ((uint32_t)((rg + 16 * j) * 128 + lq * 8));

    // ---- prologue: stage tile 0 into buffer 0
    {
        size_t go0 = (size_t)brow0 * DDIM + bcg0 * 8;
        size_t go1 = (size_t)brow1 * DDIM + bcg1 * 8;
        CP_ASYNC16(base + OFF_BHI(0) + bsw0, (const void*)(g_pHi + go0));
        CP_ASYNC16(base + OFF_BHI(0) + bsw1, (const void*)(g_pHi + go1));
        CP_ASYNC16(base + OFF_BLO(0) + bsw0, (const void*)(g_pLo + go0));
        CP_ASYNC16(base + OFF_BLO(0) + bsw1, (const void*)(g_pLo + go1));
        CP_COMMIT();
        float4 av[8];
#pragma unroll
        for (int j = 0; j < 8; j++) av[j] = *(const float4*)(aRow + (size_t)j * 16 * DDIM);
#pragma unroll
        for (int j = 0; j < 8; j++) {
            float4 v = av[j];
            e2r[j] += v.x * v.x + v.y * v.y + v.z * v.z + v.w * v.w;
            uint32_t h01 = bf16x2_of(v.x, v.y);
            uint32_t h23 = bf16x2_of(v.z, v.w);
            uint32_t l01 = bf16x2_of(v.x - hf_lo(h01), v.y - hf_hi(h01));
            uint32_t l23 = bf16x2_of(v.z - hf_lo(h23), v.w - hf_hi(h23));
            STS64(base + OFF_AHI(0) + aswj[j], h01, h23);
            STS64(base + OFF_ALO(0) + aswj[j], l01, l23);
        }
        CP_WAIT0();
        __syncthreads();
    }

    for (int kt = 0; kt < 8; kt++) {
        int cur = kt & 1, nxt = cur ^ 1;

        // ---- prefetch tile kt+1: LDG A into regs, cp.async B into nxt
        float4 av[8];
        if (kt < 7) {
            size_t go0 = (size_t)brow0 * DDIM + (kt + 1) * 64 + bcg0 * 8;
            size_t go1 = (size_t)brow1 * DDIM + (kt + 1) * 64 + bcg1 * 8;
            CP_ASYNC16(base + OFF_BHI(nxt) + bsw0, (const void*)(g_pHi + go0));
            CP_ASYNC16(base + OFF_BHI(nxt) + bsw1, (const void*)(g_pHi + go1));
            CP_ASYNC16(base + OFF_BLO(nxt) + bsw0, (const void*)(g_pLo + go0));
            CP_ASYNC16(base + OFF_BLO(nxt) + bsw1, (const void*)(g_pLo + go1));
            CP_COMMIT();
#pragma unroll
            for (int j = 0; j < 8; j++)
                av[j] = *(const float4*)(aRow + (size_t)j * 16 * DDIM + (kt + 1) * 64);
        }

        // ---- compute on buffer cur: 4 k16 steps
#pragma unroll
        for (int ks = 0; ks < 4; ks++) {
            uint32_t ah[2][4], al[2][4];
#pragma unroll
            for (int mt = 0; mt < 2; mt++) {
                uint32_t sw = SWZ((uint32_t)((Rb + 16 * mt + arowoff) * 128 + (ks * 16 + akoff) * 2));
                LDSM4(ah[mt], base + OFF_AHI(cur) + sw);
                LDSM4(al[mt], base + OFF_ALO(cur) + sw);
            }
            uint32_t bh[2][4], bl[2][4];
#pragma unroll
            for (int p = 0; p < 2; p++) {
                uint32_t sw = SWZ((uint32_t)((Cb + 16 * p + bnoff) * 128 + (ks * 16 + bkoff) * 2));
                LDSM4(bh[p], base + OFF_BHI(cur) + sw);
                LDSM4(bl[p], base + OFF_BLO(cur) + sw);
            }
#pragma unroll
            for (int mt = 0; mt < 2; mt++)
#pragma unroll
                for (int p = 0; p < 2; p++)
#pragma unroll
                    for (int q = 0; q < 2; q++) {
                        float* d = acc[mt][2 * p + q];
                        mma_bf16(d, ah[mt], bh[p][2 * q], bh[p][2 * q + 1]);
                        mma_bf16(d, ah[mt], bl[p][2 * q], bl[p][2 * q + 1]);
                        mma_bf16(d, al[mt], bh[p][2 * q], bh[p][2 * q + 1]);
                    }
        }

        // ---- convert + STS A(kt+1) into nxt
        if (kt < 7) {
#pragma unroll
            for (int j = 0; j < 8; j++) {
                float4 v = av[j];
                e2r[j] += v.x * v.x + v.y * v.y + v.z * v.z + v.w * v.w;
                uint32_t h01 = bf16x2_of(v.x, v.y);
                uint32_t h23 = bf16x2_of(v.z, v.w);
                uint32_t l01 = bf16x2_of(v.x - hf_lo(h01), v.y - hf_hi(h01));
                uint32_t l23 = bf16x2_of(v.z - hf_lo(h23), v.w - hf_hi(h23));
                STS64(base + OFF_AHI(nxt) + aswj[j], h01, h23);
                STS64(base + OFF_ALO(nxt) + aswj[j], l01, l23);
            }
            CP_WAIT0();
        }
        __syncthreads();
    }

    // ---- e2: reduce 16 lane-quarters per row via shfl (deterministic)
    float* e2row = smf + OFF_E2 / 4;
    float* p2s   = smf + OFF_P2 / 4;
    float* wl    = smf + OFF_WL / 4;
    float* wa    = smf + OFF_WA / 4;
#pragma unroll
    for (int j = 0; j < 8; j++) {
        float v = e2r[j];
        v += __shfl_xor_sync(0xffffffffu, v, 1);
        v += __shfl_xor_sync(0xffffffffu, v, 2);
        v += __shfl_xor_sync(0xffffffffu, v, 4);
        v += __shfl_xor_sync(0xffffffffu, v, 8);
        if (lq == 0) e2row[rg + 16 * j] = v;
    }
    if (t < CCLS) p2s[t] = g_p2[t];
    __syncthreads();

    // ---- logits into smf[0 .. 128*68)
    {
        int g  = lane >> 2;
        int tq = lane & 3;
#pragma unroll
        for (int mt = 0; mt < 2; mt++) {
            int r0 = Rb + 16 * mt + g;
            float e2a = e2row[r0];
            float e2b = e2row[r0 + 8];
#pragma unroll
            for (int nt = 0; nt < 4; nt++) {
                int col = Cb + 8 * nt + 2 * tq;
                float p2a = p2s[col], p2b = p2s[col + 1];
                float* d = acc[mt][nt];
                float lg0 = -sqrtf(fmaxf(e2a + p2a - 2.f * d[0], 1e-12f));
                float lg1 = -sqrtf(fmaxf(e2a + p2b - 2.f * d[1], 1e-12f));
                float lg2 = -sqrtf(fmaxf(e2b + p2a - 2.f * d[2], 1e-12f));
                float lg3 = -sqrtf(fmaxf(e2b + p2b - 2.f * d[3], 1e-12f));
                *(float2*)&smf[r0 * 68 + col]       = make_float2(lg0, lg1);
                *(float2*)&smf[(r0 + 8) * 68 + col] = make_float2(lg2, lg3);
            }
        }
    }
    __syncthreads();

    // ---- per-row softmax / NLL / argmax
    float lossAcc = 0.f, accAcc = 0.f;
    for (int j = 0; j < 16; j++) {
        int lrow = wid + 8 * j;
        float v0 = smf[lrow * 68 + lane];
        float v1 = smf[lrow * 68 + 32 + lane];
        float bv; int bi;
        if (v1 > v0) { bv = v1; bi = lane + 32; } else { bv = v0; bi = lane; }
#pragma unroll
        for (int s = 16; s > 0; s >>= 1) {
            float ov = __shfl_xor_sync(0xffffffffu, bv, s);
            int   oi = __shfl_xor_sync(0xffffffffu, bi, s);
            if (ov > bv || (ov == bv && oi < bi)) { bv = ov; bi = oi; }
        }
        float e = expf(v0 - bv) + expf(v1 - bv);
#pragma unroll
        for (int s = 16; s > 0; s >>= 1)
            e += __shfl_xor_sync(0xffffffffu, e, s);
        float lse = bv + logf(e);
        int lab = labels[blk * 128 + lrow] & (CCLS - 1);
        float lv = smf[lrow * 68 + lab];
        lossAcc += (lse - lv);
        accAcc  += (bi == lab) ? 1.f : 0.f;
    }
    if (lane == 0) { wl[wid] = lossAcc; wa[wid] = accAcc; }
    __syncthreads();

    __shared__ unsigned int sLast;
    if (t == 0) {
        float L = 0.f, A = 0.f;
#pragma unroll
        for (int ww = 0; ww < 8; ww++) { L += wl[ww]; A += wa[ww]; }
        g_bl[blk] = L;
        g_ba[blk] = A;
        __threadfence();
        unsigned int v = atomicAdd(&g_ctr, 1u);
        sLast = (v == GC - 1) ? 1u : 0u;
    }
    __syncthreads();

    if (sLast) {
        float* rl = smf;
        float* ra = smf + 512;
        float l = __ldcg(&g_bl[t]) + __ldcg(&g_bl[t + 256]);
        float a = __ldcg(&g_ba[t]) + __ldcg(&g_ba[t + 256]);
        rl[t] = l; ra[t] = a;
        __syncthreads();
        for (int s = 128; s >= 1; s >>= 1) {
            if (t < s) { rl[t] += rl[t + s]; ra[t] += ra[t + s]; }
            __syncthreads();
        }
        if (t == 0) {
            const float invN = 1.f / (float)NROWS;
            outp[0] = rl[0] * invN;
            outp[1] = ra[0] * invN;
        }
    }
}

// ============================================================
extern "C" void kernel_launch(void* const* d_in, const int* in_sizes, int n_in,
                              void* d_out, int out_size) {
    const float* emb    = (const float*)d_in[0];
    const int*   labels = (const int*)d_in[1];
    float*       out    = (float*)d_out;

    const int smemA = (CCLS * DDIM + CCLS) * (int)sizeof(float) + 512 * (int)sizeof(int);
    cudaFuncSetAttribute(kA, cudaFuncAttributeMaxDynamicSharedMemorySize, smemA);
    cudaFuncSetAttribute(kC, cudaFuncAttributeMaxDynamicSharedMemorySize, SMC_BYTES);

    kZ<<<1, 1>>>();
    kA<<<GA, 512, smemA>>>(emb, labels);
    kB<<<CCLS, 512>>>();
    kC<<<GC, 256, SMC_BYTES>>>(emb, labels, out);
}

// round 16
// speedup vs baseline: 1.5237x; 1.0371x over previous
#include <cuda_runtime.h>
#include <cuda_bf16.h>
#include <cstdint>
#include <math.h>

// Problem constants (fixed shapes)
#define NROWS 65536
#define DDIM  512
#define CCLS  64

#define GA 128                 // kernel A blocks
#define GC 512                 // kernel C blocks (128 rows each)

// ---------------- device scratch ----------------
__device__ float g_psums[GA * CCLS * DDIM];      // per-block partial class sums
__device__ float g_pcnt [GA * CCLS];             // per-block partial class counts
__device__ __nv_bfloat16 g_pHi[CCLS * DDIM];     // prototypes hi (bf16) [c][d]
__device__ __nv_bfloat16 g_pLo[CCLS * DDIM];     // prototypes lo (bf16)
__device__ float g_p2[CCLS];                     // ||p_c||^2 (fp32)
__device__ float g_bl[GC];                       // per-block loss partial
__device__ float g_ba[GC];                       // per-block accuracy partial
__device__ unsigned int g_ctr;                   // kC completion counter

// ---------------- helpers ----------------
__device__ __forceinline__ uint32_t smem_u32(const void* p) {
    uint32_t a;
    asm("{ .reg .u64 t; cvta.to.shared.u64 t, %1; cvt.u32.u64 %0, t; }" : "=r"(a) : "l"(p));
    return a;
}
__device__ __forceinline__ uint32_t bf16x2_of(float lo, float hi) {
    uint32_t r;
    asm("cvt.rn.bf16x2.f32 %0, %1, %2;" : "=r"(r) : "f"(hi), "f"(lo));
    return r;
}
__device__ __forceinline__ float hf_lo(uint32_t h) { return __uint_as_float(h << 16); }
__device__ __forceinline__ float hf_hi(uint32_t h) { return __uint_as_float(h & 0xFFFF0000u); }

// SW64 swizzle: 64-byte rows, atom = 8 rows x 64B
#define SWZ64(off) ((off) ^ (((off) >> 3) & 0x30))

#define STS64(a, r0, r1) \
    asm volatile("st.shared.v2.b32 [%0], {%1,%2};" :: "r"(a), "r"(r0), "r"(r1) : "memory")

#define CP_ASYNC16(sa, ga) \
    asm volatile("cp.async.cg.shared.global [%0], [%1], 16;" :: "r"(sa), "l"(ga) : "memory")
#define CP_COMMIT() asm volatile("cp.async.commit_group;" ::: "memory")
#define CP_WAIT0()  asm volatile("cp.async.wait_group 0;" ::: "memory")

#define LDSM4(r, a) \
    asm volatile("ldmatrix.sync.aligned.m8n8.x4.shared.b16 {%0,%1,%2,%3}, [%4];" \
        : "=r"((r)[0]), "=r"((r)[1]), "=r"((r)[2]), "=r"((r)[3]) : "r"(a))

__device__ __forceinline__ void mma_bf16(float* d, const uint32_t* a, uint32_t b0, uint32_t b1) {
    asm volatile("mma.sync.aligned.m16n8k16.row.col.f32.bf16.bf16.f32 "
        "{%0,%1,%2,%3}, {%4,%5,%6,%7}, {%8,%9}, {%0,%1,%2,%3};"
        : "+f"(d[0]), "+f"(d[1]), "+f"(d[2]), "+f"(d[3])
        : "r"(a[0]), "r"(a[1]), "r"(a[2]), "r"(a[3]), "r"(b0), "r"(b1));
}

// ============================================================
// Kernel Z: reset completion counter
// ============================================================
__global__ void kZ() { g_ctr = 0u; }

// ============================================================
// Kernel A: per-block segment sums. 512 threads, 1 f32 column
// per thread (conflict-free), depth-16 row prefetch.
// ============================================================
__global__ void __launch_bounds__(512)
kA(const float* __restrict__ emb, const int* __restrict__ labels) {
    extern __shared__ float s[];
    float* acc  = s;
    float* cnt  = s + CCLS * DDIM;
    int*   slab = (int*)(s + CCLS * DDIM + CCLS);

    int t = threadIdx.x;
    int base = blockIdx.x * 512;

    for (int i = t * 4; i < CCLS * DDIM; i += 512 * 4)
        *(float4*)(acc + i) = make_float4(0.f, 0.f, 0.f, 0.f);
    if (t < CCLS) cnt[t] = 0.f;
    slab[t] = labels[base + t] & (CCLS - 1);
    __syncthreads();

    atomicAdd(&cnt[slab[t]], 1.f);

    const float* eBase = emb + (size_t)base * DDIM + t;
    float cur[16], nxt[16];
#pragma unroll
    for (int i = 0; i < 16; i++) cur[i] = eBase[(size_t)i * DDIM];

    for (int g = 0; g < 32; g++) {
        if (g < 31) {
#pragma unroll
            for (int i = 0; i < 16; i++)
                nxt[i] = eBase[(size_t)((g + 1) * 16 + i) * DDIM];
        }
#pragma unroll
        for (int i = 0; i < 16; i++)
            acc[slab[g * 16 + i] * DDIM + t] += cur[i];
#pragma unroll
        for (int i = 0; i < 16; i++) cur[i] = nxt[i];
    }
    __syncthreads();

    float* out = g_psums + (size_t)blockIdx.x * (CCLS * DDIM);
    for (int i = t * 4; i < CCLS * DDIM; i += 512 * 4)
        *(float4*)(out + i) = *(float4*)(acc + i);
    if (t < CCLS) g_pcnt[blockIdx.x * CCLS + t] = cnt[t];
}

// ============================================================
// Kernel B: reduce partials -> prototypes (bf16 hi/lo) + p2
// ============================================================
__global__ void __launch_bounds__(512)
kB() {
    int c = blockIdx.x;
    int d = threadIdx.x;
    __shared__ float scnt[128];
    __shared__ float sred[512];

    if (d < 128) scnt[d] = g_pcnt[d * CCLS + c];
    __syncthreads();
    for (int s = 64; s >= 1; s >>= 1) {
        if (d < s) scnt[d] += scnt[d + s];
        __syncthreads();
    }
    float cnt = scnt[0];

    float sum = 0.f;
    const float* base = g_psums + (size_t)c * DDIM + d;
#pragma unroll 8
    for (int g = 0; g < GA; g++) sum += base[(size_t)g * (CCLS * DDIM)];
    float proto = sum / cnt;

    __nv_bfloat16 h = __float2bfloat16(proto);
    float hf = __bfloat162float(h);
    g_pHi[c * DDIM + d] = h;
    g_pLo[c * DDIM + d] = __float2bfloat16(proto - hf);

    sred[d] = proto * proto;
    __syncthreads();
    for (int s = 256; s >= 1; s >>= 1) {
        if (d < s) sred[d] += sred[d + s];
        __syncthreads();
    }
    if (d == 0) g_p2[c] = sred[0];
}

// ============================================================
// Kernel C: HMMA bf16 hi/lo GEMM 128x64 per CTA, K=512 in 16
//           chunks of 32 (SW64, 64B rows), double-buffered,
//           3 CTAs/SM, fused epilogue + last-block reduce
// ============================================================
#define BUFSZ      24576
#define OFF_AHI(b) ((b) * BUFSZ)               // 128 x 64B = 8KB
#define OFF_ALO(b) ((b) * BUFSZ + 8192)
#define OFF_BHI(b) ((b) * BUFSZ + 16384)       // 64 x 64B = 4KB
#define OFF_BLO(b) ((b) * BUFSZ + 20480)
#define OFF_E2    49152        // 128 floats
#define OFF_P2    49664        // 64 floats
#define OFF_WL    49920        // 8 floats
#define OFF_WA    49952        // 8 floats
#define SMC_BYTES (49984 + 1024)

__global__ void __launch_bounds__(256, 3)
kC(const float* __restrict__ emb, const int* __restrict__ labels,
   float* __restrict__ outp) {
    extern __shared__ __align__(16) unsigned char smraw[];
    uint32_t raw = smem_u32(smraw);
    uint32_t base = (raw + 1023) & ~1023u;
    float* smf = (float*)(smraw + (base - raw));

    const int t = threadIdx.x;
    const int wid = t >> 5, lane = t & 31;
    const int blk = blockIdx.x;

    const int Rb = (wid >> 1) * 32;
    const int Cb = (wid & 1) * 32;

    // ---- coalesced A-loader: rg = t>>3 (0..31), lq = t&7 (col quad)
    //      round j (0..3): row rg + 32j, cols lq*4..+3 within 32-chunk
    const int rg = t >> 3;
    const int lq = t & 7;
    const float* aRow = emb + ((size_t)(blk * 128 + rg)) * DDIM + lq * 4;
    float e2r[4] = {0.f, 0.f, 0.f, 0.f};

    float acc[2][4][4];
#pragma unroll
    for (int i = 0; i < 2; i++)
#pragma unroll
        for (int j = 0; j < 4; j++)
#pragma unroll
            for (int k = 0; k < 4; k++) acc[i][j][k] = 0.f;

    const int arowoff = (lane & 7) + ((lane >> 3) & 1) * 8;
    const int akoff   = ((lane >> 4) & 1) * 8;
    const int bnoff   = (lane & 7) + ((lane >> 4) & 1) * 8;
    const int bkoff   = ((lane >> 3) & 1) * 8;

    // B loader: 1 x 16B chunk per thread per (hi|lo): row t>>2, chunk t&3
    const int brow = t >> 2, bcg = t & 3;
    const uint32_t bsw = SWZ64((uint32_t)(brow * 64 + bcg * 16));
    const size_t bgo = (size_t)brow * DDIM + bcg * 8;

    // A STS offsets per round j
    uint32_t aswj[4];
#pragma unroll
    for (int j = 0; j < 4; j++)
        aswj[j] = SWZ64((uint32_t)((rg + 32 * j) * 64 + lq * 8));

    // ---- prologue: stage tile 0 into buffer 0
    {
        CP_ASYNC16(base + OFF_BHI(0) + bsw, (const void*)(g_pHi + bgo));
        CP_ASYNC16(base + OFF_BLO(0) + bsw, (const void*)(g_pLo + bgo));
        CP_COMMIT();
        float4 av[4];
#pragma unroll
        for (int j = 0; j < 4; j++) av[j] = *(const float4*)(aRow + (size_t)j * 32 * DDIM);
#pragma unroll
        for (int j = 0; j < 4; j++) {
            float4 v = av[j];
            e2r[j] += v.x * v.x + v.y * v.y + v.z * v.z + v.w * v.w;
            uint32_t h01 = bf16x2_of(v.x, v.y);
            uint32_t h23 = bf16x2_of(v.z, v.w);
            uint32_t l01 = bf16x2_of(v.x - hf_lo(h01), v.y - hf_hi(h01));
            uint32_t l23 = bf16x2_of(v.z - hf_lo(h23), v.w - hf_hi(h23));
            STS64(base + OFF_AHI(0) + aswj[j], h01, h23);
            STS64(base + OFF_ALO(0) + aswj[j], l01, l23);
        }
        CP_WAIT0();
        __syncthreads();
    }

    for (int kt = 0; kt < 16; kt++) {
        int cur = kt & 1, nxt = cur ^ 1;

        // ---- prefetch tile kt+1
        float4 av[4];
        if (kt < 15) {
            size_t go = bgo + (kt + 1) * 32;
            CP_ASYNC16(base + OFF_BHI(nxt) + bsw, (const void*)(g_pHi + go));
            CP_ASYNC16(base + OFF_BLO(nxt) + bsw, (const void*)(g_pLo + go));
            CP_COMMIT();
#pragma unroll
            for (int j = 0; j < 4; j++)
                av[j] = *(const float4*)(aRow + (size_t)j * 32 * DDIM + (kt + 1) * 32);
        }

        // ---- compute on buffer cur: 2 k16 steps
#pragma unroll
        for (int ks = 0; ks < 2; ks++) {
            uint32_t ah[2][4], al[2][4];
#pragma unroll
            for (int mt = 0; mt < 2; mt++) {
                uint32_t sw = SWZ64((uint32_t)((Rb + 16 * mt + arowoff) * 64 + (ks * 16 + akoff) * 2));
                LDSM4(ah[mt], base + OFF_AHI(cur) + sw);
                LDSM4(al[mt], base + OFF_ALO(cur) + sw);
            }
            uint32_t bh[2][4], bl[2][4];
#pragma unroll
            for (int p = 0; p < 2; p++) {
                uint32_t sw = SWZ64((uint32_t)((Cb + 16 * p + bnoff) * 64 + (ks * 16 + bkoff) * 2));
                LDSM4(bh[p], base + OFF_BHI(cur) + sw);
                LDSM4(bl[p], base + OFF_BLO(cur) + sw);
            }
#pragma unroll
            for (int mt = 0; mt < 2; mt++)
#pragma unroll
                for (int p = 0; p < 2; p++)
#pragma unroll
                    for (int q = 0; q < 2; q++) {
                        float* d = acc[mt][2 * p + q];
                        mma_bf16(d, ah[mt], bh[p][2 * q], bh[p][2 * q + 1]);
                        mma_bf16(d, ah[mt], bl[p][2 * q], bl[p][2 * q + 1]);
                        mma_bf16(d, al[mt], bh[p][2 * q], bh[p][2 * q + 1]);
                    }
        }

        // ---- convert + STS A(kt+1) into nxt
        if (kt < 15) {
#pragma unroll
            for (int j = 0; j < 4; j++) {
                float4 v = av[j];
                e2r[j] += v.x * v.x + v.y * v.y + v.z * v.z + v.w * v.w;
                uint32_t h01 = bf16x2_of(v.x, v.y);
                uint32_t h23 = bf16x2_of(v.z, v.w);
                uint32_t l01 = bf16x2_of(v.x - hf_lo(h01), v.y - hf_hi(h01));
                uint32_t l23 = bf16x2_of(v.z - hf_lo(h23), v.w - hf_hi(h23));
                STS64(base + OFF_AHI(nxt) + aswj[j], h01, h23);
                STS64(base + OFF_ALO(nxt) + aswj[j], l01, l23);
            }
            CP_WAIT0();
        }
        __syncthreads();
    }

    // ---- e2: reduce 8 lane-quads per row via shfl (deterministic)
    float* e2row = smf + OFF_E2 / 4;
    float* p2s   = smf + OFF_P2 / 4;
    float* wl    = smf + OFF_WL / 4;
    float* wa    = smf + OFF_WA / 4;
#pragma unroll
    for (int j = 0; j < 4; j++) {
        float v = e2r[j];
        v += __shfl_xor_sync(0xffffffffu, v, 1);
        v += __shfl_xor_sync(0xffffffffu, v, 2);
        v += __shfl_xor_sync(0xffffffffu, v, 4);
        if ((lane & 7) == 0) e2row[rg + 32 * j] = v;
    }
    if (t < CCLS) p2s[t] = g_p2[t];
    __syncthreads();

    // ---- logits into smf[0 .. 128*68)
    {
        int g  = lane >> 2;
        int tq = lane & 3;
#pragma unroll
        for (int mt = 0; mt < 2; mt++) {
            int r0 = Rb + 16 * mt + g;
            float e2a = e2row[r0];
            float e2b = e2row[r0 + 8];
#pragma unroll
            for (int nt = 0; nt < 4; nt++) {
                int col = Cb + 8 * nt + 2 * tq;
                float p2a = p2s[col], p2b = p2s[col + 1];
                float* d = acc[mt][nt];
                float lg0 = -sqrtf(fmaxf(e2a + p2a - 2.f * d[0], 1e-12f));
                float lg1 = -sqrtf(fmaxf(e2a + p2b - 2.f * d[1], 1e-12f));
                float lg2 = -sqrtf(fmaxf(e2b + p2a - 2.f * d[2], 1e-12f));
                float lg3 = -sqrtf(fmaxf(e2b + p2b - 2.f * d[3], 1e-12f));
                *(float2*)&smf[r0 * 68 + col]       = make_float2(lg0, lg1);
                *(float2*)&smf[(r0 + 8) * 68 + col] = make_float2(lg2, lg3);
            }
        }
    }
    __syncthreads();

    // ---- per-row softmax / NLL / argmax
    float lossAcc = 0.f, accAcc = 0.f;
    for (int j = 0; j < 16; j++) {
        int lrow = wid + 8 * j;
        float v0 = smf[lrow * 68 + lane];
        float v1 = smf[lrow * 68 + 32 + lane];
        float bv; int bi;
        if (v1 > v0) { bv = v1; bi = lane + 32; } else { bv = v0; bi = lane; }
#pragma unroll
        for (int s = 16; s > 0; s >>= 1) {
            float ov = __shfl_xor_sync(0xffffffffu, bv, s);
            int   oi = __shfl_xor_sync(0xffffffffu, bi, s);
            if (ov > bv || (ov == bv && oi < bi)) { bv = ov; bi = oi; }
        }
        float e = expf(v0 - bv) + expf(v1 - bv);
#pragma unroll
        for (int s = 16; s > 0; s >>= 1)
            e += __shfl_xor_sync(0xffffffffu, e, s);
        float lse = bv + logf(e);
        int lab = labels[blk * 128 + lrow] & (CCLS - 1);
        float lv = smf[lrow * 68 + lab];
        lossAcc += (lse - lv);
        accAcc  += (bi == lab) ? 1.f : 0.f;
    }
    if (lane == 0) { wl[wid] = lossAcc; wa[wid] = accAcc; }
    __syncthreads();

    __shared__ unsigned int sLast;
    if (t == 0) {
        float L = 0.f, A = 0.f;
#pragma unroll
        for (int ww = 0; ww < 8; ww++) { L += wl[ww]; A += wa[ww]; }
        g_bl[blk] = L;
        g_ba[blk] = A;
        __threadfence();
        unsigned int v = atomicAdd(&g_ctr, 1u);
        sLast = (v == GC - 1) ? 1u : 0u;
    }
    __syncthreads();

    if (sLast) {
        float* rl = smf;
        float* ra = smf + 512;
        float l = __ldcg(&g_bl[t]) + __ldcg(&g_bl[t + 256]);
        float a = __ldcg(&g_ba[t]) + __ldcg(&g_ba[t + 256]);
        rl[t] = l; ra[t] = a;
        __syncthreads();
        for (int s = 128; s >= 1; s >>= 1) {
            if (t < s) { rl[t] += rl[t + s]; ra[t] += ra[t + s]; }
            __syncthreads();
        }
        if (t == 0) {
            const float invN = 1.f / (float)NROWS;
            outp[0] = rl[0] * invN;
            outp[1] = ra[0] * invN;
        }
    }
}

// ============================================================
extern "C" void kernel_launch(void* const* d_in, const int* in_sizes, int n_in,
                              void* d_out, int out_size) {
    const float* emb    = (const float*)d_in[0];
    const int*   labels = (const int*)d_in[1];
    float*       out    = (float*)d_out;

    const int smemA = (CCLS * DDIM + CCLS) * (int)sizeof(float) + 512 * (int)sizeof(int);
    cudaFuncSetAttribute(kA, cudaFuncAttributeMaxDynamicSharedMemorySize, smemA);
    cudaFuncSetAttribute(kC, cudaFuncAttributeMaxDynamicSharedMemorySize, SMC_BYTES);

    kZ<<<1, 1>>>();
    kA<<<GA, 512, smemA>>>(emb, labels);
    kB<<<CCLS, 512>>>();
    kC<<<GC, 256, SMC_BYTES>>>(emb, labels, out);
}